// round 2
// baseline (speedup 1.0000x reference)
#include <cuda_runtime.h>
#include <cuda_bf16.h>

// Problem constants (fixed by the dataset)
#define NN     401408          // nodes
#define EE     3211264         // edges
#define CAP    40              // slots per node (Binomial(E,1/N)~Poisson(8) indegree)
#define OVF_CAP 65536
#define KTOT   50176           // 784*64
#define SPLITS 32
#define KC     (KTOT/SPLITS)   // 1568
#define BK     16
#define BM     64

// ---------------- device scratch (static, no allocations) ----------------
__device__ int   g_cnt[NN];
__device__ float g_dinv[NN];
__device__ int   g_slots[(size_t)NN * CAP];
__device__ float g_t[NN];
__device__ __align__(16) float g_h1[(size_t)NN * 32];
__device__ __align__(16) float g_h2[(size_t)NN * 64];
__device__ __align__(16) float g_part[(size_t)SPLITS * 512 * 128];
__device__ int   g_ovf_n;
__device__ int   g_is64;
__device__ int   g_ovf_src[OVF_CAP];
__device__ int   g_ovf_dst[OVF_CAP];

// ---------------- kernels ----------------

// Detect edge_index dtype: int64 values < 2^31 have all-zero high words.
__global__ void k_dtype(const int* __restrict__ ei) {
    if (threadIdx.x == 0 && blockIdx.x == 0) {
        int ok = 1;
        for (int i = 0; i < 64; i++)
            if (ei[2 * i + 1] != 0) { ok = 0; break; }
        g_is64 = ok;
    }
}

__global__ void k_init(int n) {
    if (blockIdx.x == 0 && threadIdx.x == 0) g_ovf_n = 0;
    for (int i = blockIdx.x * blockDim.x + threadIdx.x; i < n;
         i += gridDim.x * blockDim.x)
        g_cnt[i] = 0;
}

// Count in-degree and fill per-node slot table with source indices.
__global__ void k_count(const int* __restrict__ ei, int E) {
    int e = blockIdx.x * blockDim.x + threadIdx.x;
    if (e >= E) return;
    int s, d;
    if (g_is64) {                      // little-endian low words
        s = ei[2 * (size_t)e];
        d = ei[2 * ((size_t)E + e)];
    } else {
        s = ei[e];
        d = ei[(size_t)E + e];
    }
    if ((unsigned)s >= (unsigned)NN || (unsigned)d >= (unsigned)NN) return;
    int c = atomicAdd(&g_cnt[d], 1);
    if (c < CAP) {
        g_slots[(size_t)d * CAP + c] = s;
    } else {
        int o = atomicAdd(&g_ovf_n, 1);
        if (o < OVF_CAP) { g_ovf_src[o] = s; g_ovf_dst[o] = d; }
    }
}

__global__ void k_dinv(int n) {
    int i = blockIdx.x * blockDim.x + threadIdx.x;
    if (i < n) g_dinv[i] = rsqrtf(1.0f + (float)g_cnt[i]);
}

// Layer-1 scalar aggregation: g_t[i] = sum_{src->i} x[src]*dinv[src]
__global__ void k_l1a(const float* __restrict__ x, int n) {
    int i = blockIdx.x * blockDim.x + threadIdx.x;
    if (i >= n) return;
    int c = g_cnt[i];
    int m = c < CAP ? c : CAP;
    size_t base = (size_t)i * CAP;
    float sum = 0.f;
    for (int j = 0; j < m; j++) {
        int s = g_slots[base + j];
        sum += x[s] * g_dinv[s];
    }
    if (c > CAP) {  // exact-correctness path; essentially never taken
        int on = g_ovf_n; if (on > OVF_CAP) on = OVF_CAP;
        for (int e = 0; e < on; e++)
            if (g_ovf_dst[e] == i) {
                int s = g_ovf_src[e];
                sum += x[s] * g_dinv[s];
            }
    }
    g_t[i] = sum;
}

// h1[i,f] = relu(T[i]*W1[f] + b1[f]), T[i] = dinv[i]*(g_t[i] + x[i]*dinv[i])
__global__ void k_l1b(const float* __restrict__ x,
                      const float* __restrict__ W1,
                      const float* __restrict__ b1, int n) {
    __shared__ float w[32], b[32];
    if (threadIdx.x < 32) { w[threadIdx.x] = W1[threadIdx.x]; b[threadIdx.x] = b1[threadIdx.x]; }
    __syncthreads();
    int idx = blockIdx.x * blockDim.x + threadIdx.x;   // over n*8
    int node = idx >> 3, q = idx & 7;
    if (node >= n) return;
    float di = g_dinv[node];
    float tt = di * (g_t[node] + x[node] * di);
    int f = q * 4;
    float4 r;
    r.x = fmaxf(tt * w[f + 0] + b[f + 0], 0.f);
    r.y = fmaxf(tt * w[f + 1] + b[f + 1], 0.f);
    r.z = fmaxf(tt * w[f + 2] + b[f + 2], 0.f);
    r.w = fmaxf(tt * w[f + 3] + b[f + 3], 0.f);
    ((float4*)g_h1)[idx] = r;
}

// Layer-2: warp per node. 32-dim gather-aggregate, then 32x64 W2 + bias + relu.
__global__ void k_l2(const float* __restrict__ W2,
                     const float* __restrict__ b2, int n) {
    __shared__ float w2s[32 * 64];
    __shared__ float b2s[64];
    for (int idx = threadIdx.x; idx < 2048; idx += blockDim.x) w2s[idx] = W2[idx];
    if (threadIdx.x < 64) b2s[threadIdx.x] = b2[threadIdx.x];
    __syncthreads();

    int warp = threadIdx.x >> 5, lane = threadIdx.x & 31;
    int i = blockIdx.x * 8 + warp;
    if (i >= n) return;

    float di = g_dinv[i];
    int c = g_cnt[i];
    int m = c < CAP ? c : CAP;
    size_t base = (size_t)i * CAP;
    float acc = 0.f;
    for (int j = 0; j < m; j++) {
        int s = g_slots[base + j];           // broadcast load
        acc += g_h1[(size_t)s * 32 + lane] * g_dinv[s];
    }
    if (c > CAP) {
        int on = g_ovf_n; if (on > OVF_CAP) on = OVF_CAP;
        for (int e = 0; e < on; e++)
            if (g_ovf_dst[e] == i) {
                int s = g_ovf_src[e];
                acc += g_h1[(size_t)s * 32 + lane] * g_dinv[s];
            }
    }
    float u = di * acc + g_h1[(size_t)i * 32 + lane] * di * di;

    float o0 = b2s[lane], o1 = b2s[lane + 32];
#pragma unroll
    for (int f = 0; f < 32; f++) {
        float uf = __shfl_sync(0xffffffffu, u, f);
        o0 += uf * w2s[f * 64 + lane];
        o1 += uf * w2s[f * 64 + lane + 32];
    }
    g_h2[(size_t)i * 64 + lane]      = fmaxf(o0, 0.f);
    g_h2[(size_t)i * 64 + lane + 32] = fmaxf(o1, 0.f);
}

// Split-K fp32 GEMM: [512 x 50176] (g_h2 flat) @ [50176 x 128] (fc1_w)
// grid = (8 M-tiles, 32 K-splits); each block writes its disjoint partial slice.
__global__ void __launch_bounds__(256) k_gemm(const float* __restrict__ B) {
    __shared__ __align__(16) float As[BM * BK];      // 64x16
    __shared__ __align__(16) float Bs[BK * 128];     // 16x128
    int bm = blockIdx.x, sp = blockIdx.y;
    int g0 = bm * BM;
    int k0 = sp * KC;
    int t = threadIdx.x;
    int tx = t & 31, ty = t >> 5;

    float acc[8][4];
#pragma unroll
    for (int i = 0; i < 8; i++)
#pragma unroll
        for (int j = 0; j < 4; j++) acc[i][j] = 0.f;

    for (int kt = 0; kt < KC; kt += BK) {
        {   // A tile: 64x16 = 256 float4, one per thread
            int row = t >> 2, c4 = t & 3;
            float4 v = *(const float4*)(g_h2 + (size_t)(g0 + row) * KTOT + k0 + kt + c4 * 4);
            *(float4*)(As + row * BK + c4 * 4) = v;
        }
#pragma unroll
        for (int r = 0; r < 2; r++) {   // B tile: 16x128 = 512 float4, two per thread
            int f4 = t * 2 + r;
            int row = f4 >> 5, c4 = f4 & 31;
            float4 v = *(const float4*)(B + (size_t)(k0 + kt + row) * 128 + c4 * 4);
            *(float4*)(Bs + row * 128 + c4 * 4) = v;
        }
        __syncthreads();
#pragma unroll
        for (int kk = 0; kk < BK; kk++) {
            float4 bv = *(float4*)(Bs + kk * 128 + tx * 4);
#pragma unroll
            for (int i = 0; i < 8; i++) {
                float a = As[(ty * 8 + i) * BK + kk];   // broadcast within warp
                acc[i][0] += a * bv.x;
                acc[i][1] += a * bv.y;
                acc[i][2] += a * bv.z;
                acc[i][3] += a * bv.w;
            }
        }
        __syncthreads();
    }
#pragma unroll
    for (int i = 0; i < 8; i++) {
        float4 v = make_float4(acc[i][0], acc[i][1], acc[i][2], acc[i][3]);
        *(float4*)(g_part + ((size_t)sp * 512 + g0 + ty * 8 + i) * 128 + tx * 4) = v;
    }
}

// Reduce partials + fc1 bias + relu + fc2
__global__ void k_final(const float* __restrict__ fc1_b,
                        const float* __restrict__ fc2_w,
                        const float* __restrict__ fc2_b,
                        float* __restrict__ out) {
    int g = blockIdx.x;     // 512
    int j = threadIdx.x;    // 128
    float v = fc1_b[j];
    for (int s = 0; s < SPLITS; s++)
        v += g_part[((size_t)s * 512 + g) * 128 + j];
    v = fmaxf(v, 0.f);
    __shared__ float f1[128];
    f1[j] = v;
    __syncthreads();
    if (j < 10) {
        float o = fc2_b[j];
#pragma unroll 16
        for (int t = 0; t < 128; t++) o += f1[t] * fc2_w[t * 10 + j];
        out[g * 10 + j] = o;
    }
}

// ---------------- host launcher ----------------
extern "C" void kernel_launch(void* const* d_in, const int* in_sizes, int n_in,
                              void* d_out, int out_size) {
    const float* x     = (const float*)d_in[0];
    const int*   ei    = (const int*)d_in[1];     // int32 OR int64 (auto-detected)
    const float* W1    = (const float*)d_in[2];
    const float* b1    = (const float*)d_in[3];
    const float* W2    = (const float*)d_in[4];
    const float* b2    = (const float*)d_in[5];
    const float* fc1_w = (const float*)d_in[6];
    const float* fc1_b = (const float*)d_in[7];
    const float* fc2_w = (const float*)d_in[8];
    const float* fc2_b = (const float*)d_in[9];
    float* out = (float*)d_out;

    int n = in_sizes[0];          // 401408
    int E = in_sizes[1] / 2;      // 3211264

    k_dtype<<<1, 32>>>(ei);
    k_init<<<1568, 256>>>(n);
    k_count<<<(E + 255) / 256, 256>>>(ei, E);
    k_dinv<<<(n + 255) / 256, 256>>>(n);
    k_l1a<<<(n + 255) / 256, 256>>>(x, n);
    k_l1b<<<(n * 8 + 255) / 256, 256>>>(x, W1, b1, n);
    k_l2<<<(n + 7) / 8, 256>>>(W2, b2, n);
    k_gemm<<<dim3(512 / BM, SPLITS), 256>>>(fc1_w);
    k_final<<<512, 128>>>(fc1_b, fc2_w, fc2_b, out);
}

// round 3
// speedup vs baseline: 1.2559x; 1.2559x over previous
#include <cuda_runtime.h>
#include <cuda_bf16.h>

// Problem constants (fixed by the dataset)
#define NN     401408          // nodes
#define EE     3211264         // edges
#define CAP    40              // slots per node (indegree ~ Poisson(8))
#define OVF_CAP 65536
#define KTOT   50176           // 784*64
#define NGRAPH 512
#define SPLITS 74              // split-K partitions (uneven: first 28 get 43 tiles, rest 42)
#define GBK    16
#define NKT    (KTOT/GBK)      // 3136 k-tiles

typedef unsigned long long u64;

// ---------------- device scratch (static, no allocations) ----------------
__device__ int   g_cnt[NN];
__device__ float g_dinv[NN];
__device__ int   g_slots[(size_t)CAP * NN];                    // slot-major
__device__ __align__(16) float g_h1[(size_t)NN * 32];
__device__ __align__(16) float g_h2t[(size_t)KTOT * NGRAPH];   // A^T: [k][g]
__device__ __align__(16) float g_part[(size_t)SPLITS * NGRAPH * 128];
__device__ int   g_ovf_n;
__device__ int   g_is64;
__device__ int   g_ovf_src[OVF_CAP];
__device__ int   g_ovf_dst[OVF_CAP];

// ---------------- ptx helpers ----------------
__device__ __forceinline__ u64 pack2(float lo, float hi) {
    u64 r; asm("mov.b64 %0, {%1, %2};" : "=l"(r) : "f"(lo), "f"(hi)); return r;
}
__device__ __forceinline__ float2 unpack2(u64 v) {
    float2 f; asm("mov.b64 {%0, %1}, %2;" : "=f"(f.x), "=f"(f.y) : "l"(v)); return f;
}
__device__ __forceinline__ void ffma2(u64& d, u64 a, u64 b) {
    asm("fma.rn.f32x2 %0, %1, %2, %0;" : "+l"(d) : "l"(a), "l"(b));
}
__device__ __forceinline__ void cp16(void* smem, const void* g) {
    unsigned sa = (unsigned)__cvta_generic_to_shared(smem);
    asm volatile("cp.async.cg.shared.global [%0], [%1], 16;" :: "r"(sa), "l"(g));
}
#define CP_COMMIT() asm volatile("cp.async.commit_group;")
#define CP_WAIT(n)  asm volatile("cp.async.wait_group %0;" :: "n"(n))

// ---------------- kernels ----------------

// Zero counts + detect edge_index dtype (int64 low/high word pattern).
__global__ void k_init(const int* __restrict__ ei, int n) {
    if (blockIdx.x == 0 && threadIdx.x == 0) {
        g_ovf_n = 0;
        int ok = 1;
        for (int i = 0; i < 64; i++)
            if (ei[2 * i + 1] != 0) { ok = 0; break; }
        g_is64 = ok;
    }
    for (int i = blockIdx.x * blockDim.x + threadIdx.x; i < n;
         i += gridDim.x * blockDim.x)
        g_cnt[i] = 0;
}

// Count in-degree and fill slot-major per-node slot table with sources.
__global__ void k_count(const int* __restrict__ ei, int E) {
    int e = blockIdx.x * blockDim.x + threadIdx.x;
    if (e >= E) return;
    int s, d;
    if (g_is64) {
        s = ei[2 * (size_t)e];
        d = ei[2 * ((size_t)E + e)];
    } else {
        s = ei[e];
        d = ei[(size_t)E + e];
    }
    if ((unsigned)s >= (unsigned)NN || (unsigned)d >= (unsigned)NN) return;
    int c = atomicAdd(&g_cnt[d], 1);
    if (c < CAP) {
        g_slots[(size_t)c * NN + d] = s;
    } else {
        int o = atomicAdd(&g_ovf_n, 1);
        if (o < OVF_CAP) { g_ovf_src[o] = s; g_ovf_dst[o] = d; }
    }
}

__global__ void k_dinv(int n) {
    int i = blockIdx.x * blockDim.x + threadIdx.x;
    if (i < n) g_dinv[i] = rsqrtf(1.0f + (float)g_cnt[i]);
}

// Fused layer-1: scalar aggregate (coalesced slot-major reads) + expand to 32 feats.
__global__ void k_l1(const float* __restrict__ x,
                     const float* __restrict__ W1,
                     const float* __restrict__ b1, int n) {
    __shared__ float w[32], b[32];
    if (threadIdx.x < 32) { w[threadIdx.x] = W1[threadIdx.x]; b[threadIdx.x] = b1[threadIdx.x]; }
    __syncthreads();
    int i = blockIdx.x * blockDim.x + threadIdx.x;
    if (i >= n) return;
    int c = g_cnt[i];
    int m = c < CAP ? c : CAP;
    float sum = 0.f;
    for (int j = 0; j < m; j++) {
        int s = g_slots[(size_t)j * NN + i];   // coalesced across threads
        sum += x[s] * g_dinv[s];
    }
    if (c > CAP) {   // exactness path; essentially never taken
        int on = g_ovf_n; if (on > OVF_CAP) on = OVF_CAP;
        for (int e = 0; e < on; e++)
            if (g_ovf_dst[e] == i) {
                int s = g_ovf_src[e];
                sum += x[s] * g_dinv[s];
            }
    }
    float di = g_dinv[i];
    float tt = di * (sum + x[i] * di);
    float4* dst = (float4*)(g_h1 + (size_t)i * 32);
#pragma unroll
    for (int q = 0; q < 8; q++) {
        int f = q * 4;
        float4 r;
        r.x = fmaxf(tt * w[f + 0] + b[f + 0], 0.f);
        r.y = fmaxf(tt * w[f + 1] + b[f + 1], 0.f);
        r.z = fmaxf(tt * w[f + 2] + b[f + 2], 0.f);
        r.w = fmaxf(tt * w[f + 3] + b[f + 3], 0.f);
        dst[q] = r;
    }
}

// Layer-2: block = 32 nodes (fixed p, consecutive graphs g). Warp per 4 nodes.
// 32-dim gather-aggregate + 32x64 W2 + bias + relu, staged and written
// TRANSPOSED into g_h2t[k][g] (K-major A for the GEMM), fully coalesced.
__global__ void __launch_bounds__(256) k_l2(const float* __restrict__ W2,
                                            const float* __restrict__ b2) {
    __shared__ float w2s[2048];
    __shared__ float b2s[64];
    __shared__ float h2t[32][65];   // [g_local][feat], padded
    int t = threadIdx.x;
    for (int idx = t; idx < 2048; idx += 256) w2s[idx] = W2[idx];
    if (t < 64) b2s[t] = b2[t];
    __syncthreads();

    int warp = t >> 5, lane = t & 31;
    int p = blockIdx.x;          // 0..783 node-in-graph
    int gblk = blockIdx.y;       // 0..15 graph block

#pragma unroll 1
    for (int q = 0; q < 4; q++) {
        int gl = warp * 4 + q;
        int i = (gblk * 32 + gl) * 784 + p;
        float di = g_dinv[i];
        int c = g_cnt[i];
        int m = c < CAP ? c : CAP;
        float acc = 0.f;
        for (int j = 0; j < m; j++) {
            int s = g_slots[(size_t)j * NN + i];     // uniform -> broadcast
            acc += g_h1[(size_t)s * 32 + lane] * g_dinv[s];
        }
        if (c > CAP) {
            int on = g_ovf_n; if (on > OVF_CAP) on = OVF_CAP;
            for (int e = 0; e < on; e++)
                if (g_ovf_dst[e] == i) {
                    int s = g_ovf_src[e];
                    acc += g_h1[(size_t)s * 32 + lane] * g_dinv[s];
                }
        }
        float u = di * acc + g_h1[(size_t)i * 32 + lane] * di * di;

        float o0 = b2s[lane], o1 = b2s[lane + 32];
#pragma unroll
        for (int f = 0; f < 32; f++) {
            float uf = __shfl_sync(0xffffffffu, u, f);
            o0 += uf * w2s[f * 64 + lane];
            o1 += uf * w2s[f * 64 + lane + 32];
        }
        h2t[gl][lane]      = fmaxf(o0, 0.f);
        h2t[gl][lane + 32] = fmaxf(o1, 0.f);
    }
    __syncthreads();
    // transposed write-out: row = feature k = p*64+f, 32 consecutive g
    for (int idx = t; idx < 2048; idx += 256) {
        int f = idx >> 5, gl = idx & 31;
        g_h2t[(size_t)(p * 64 + f) * NGRAPH + gblk * 32 + gl] = h2t[gl][f];
    }
}

// Split-K fp32 GEMM with packed f32x2 FMA + cp.async double buffering.
// C[512x128] = A^T' (g_h2t[k][g]) x B (fc1_w[k][j]).
// grid = (4 M-tiles of 128 graphs, 74 K-splits).
__global__ void __launch_bounds__(256) k_gemm(const float* __restrict__ B) {
    __shared__ __align__(16) float As[2][GBK * 128];   // [kk][g]
    __shared__ __align__(16) float Bs[2][GBK * 128];   // [kk][j]
    const int t = threadIdx.x;
    const int warp = t >> 5, lane = t & 31;
    const int g0 = blockIdx.x * 128;
    const int sp = blockIdx.y;
    const int t0 = sp * 42 + (sp < 28 ? sp : 28);
    const int nt = 42 + (sp < 28 ? 1 : 0);

    u64 acc[8][4];
#pragma unroll
    for (int i = 0; i < 8; i++)
#pragma unroll
        for (int j = 0; j < 4; j++) acc[i][j] = 0ull;

    // per-thread load slots: two 16B segments each for A and B
    const int r0 = t >> 5,        s0 = t & 31;          // e = t
    const int r1 = (t + 256) >> 5, s1 = (t + 256) & 31; // e = t+256

#pragma unroll 1
    for (int tile = 0; tile < nt; tile++) {
        if (tile == 0) {
            int k0 = t0 * GBK;
            cp16(&As[0][r0 * 128 + s0 * 4], g_h2t + (size_t)(k0 + r0) * NGRAPH + g0 + s0 * 4);
            cp16(&As[0][r1 * 128 + s1 * 4], g_h2t + (size_t)(k0 + r1) * NGRAPH + g0 + s1 * 4);
            cp16(&Bs[0][r0 * 128 + s0 * 4], B + (size_t)(k0 + r0) * 128 + s0 * 4);
            cp16(&Bs[0][r1 * 128 + s1 * 4], B + (size_t)(k0 + r1) * 128 + s1 * 4);
            CP_COMMIT();
        }
        if (tile + 1 < nt) {
            int k0 = (t0 + tile + 1) * GBK;
            int nb = (tile + 1) & 1;
            cp16(&As[nb][r0 * 128 + s0 * 4], g_h2t + (size_t)(k0 + r0) * NGRAPH + g0 + s0 * 4);
            cp16(&As[nb][r1 * 128 + s1 * 4], g_h2t + (size_t)(k0 + r1) * NGRAPH + g0 + s1 * 4);
            cp16(&Bs[nb][r0 * 128 + s0 * 4], B + (size_t)(k0 + r0) * 128 + s0 * 4);
            cp16(&Bs[nb][r1 * 128 + s1 * 4], B + (size_t)(k0 + r1) * 128 + s1 * 4);
            CP_COMMIT();
            CP_WAIT(1);
        } else {
            CP_WAIT(0);
        }
        __syncthreads();

        const int buf = tile & 1;
#pragma unroll
        for (int kk = 0; kk < GBK; kk++) {
            float4 bv = *(const float4*)&Bs[buf][kk * 128 + lane * 4];
            u64 bp0 = pack2(bv.x, bv.x);
            u64 bp1 = pack2(bv.y, bv.y);
            u64 bp2 = pack2(bv.z, bv.z);
            u64 bp3 = pack2(bv.w, bv.w);
            const float* ar = &As[buf][kk * 128 + (warp << 4)];
#pragma unroll
            for (int rp = 0; rp < 8; rp++) {
                u64 ap = *(const u64*)(ar + 2 * rp);   // two adjacent graph rows
                ffma2(acc[rp][0], ap, bp0);
                ffma2(acc[rp][1], ap, bp1);
                ffma2(acc[rp][2], ap, bp2);
                ffma2(acc[rp][3], ap, bp3);
            }
        }
        __syncthreads();
    }

#pragma unroll
    for (int rp = 0; rp < 8; rp++) {
        int grow = g0 + (warp << 4) + 2 * rp;
        float2 c0 = unpack2(acc[rp][0]);
        float2 c1 = unpack2(acc[rp][1]);
        float2 c2 = unpack2(acc[rp][2]);
        float2 c3 = unpack2(acc[rp][3]);
        float4 lo = make_float4(c0.x, c1.x, c2.x, c3.x);
        float4 hi = make_float4(c0.y, c1.y, c2.y, c3.y);
        *(float4*)&g_part[((size_t)sp * NGRAPH + grow)     * 128 + lane * 4] = lo;
        *(float4*)&g_part[((size_t)sp * NGRAPH + grow + 1) * 128 + lane * 4] = hi;
    }
}

// Reduce partials + fc1 bias + relu + fc2
__global__ void k_final(const float* __restrict__ fc1_b,
                        const float* __restrict__ fc2_w,
                        const float* __restrict__ fc2_b,
                        float* __restrict__ out) {
    int g = blockIdx.x;     // 512
    int j = threadIdx.x;    // 128
    float v = fc1_b[j];
#pragma unroll 2
    for (int s = 0; s < SPLITS; s++)
        v += g_part[((size_t)s * NGRAPH + g) * 128 + j];
    v = fmaxf(v, 0.f);
    __shared__ float f1[128];
    f1[j] = v;
    __syncthreads();
    if (j < 10) {
        float o = fc2_b[j];
#pragma unroll 16
        for (int tt = 0; tt < 128; tt++) o += f1[tt] * fc2_w[tt * 10 + j];
        out[g * 10 + j] = o;
    }
}

// ---------------- host launcher ----------------
extern "C" void kernel_launch(void* const* d_in, const int* in_sizes, int n_in,
                              void* d_out, int out_size) {
    const float* x     = (const float*)d_in[0];
    const int*   ei    = (const int*)d_in[1];     // int32 OR int64 (auto-detected)
    const float* W1    = (const float*)d_in[2];
    const float* b1    = (const float*)d_in[3];
    const float* W2    = (const float*)d_in[4];
    const float* b2    = (const float*)d_in[5];
    const float* fc1_w = (const float*)d_in[6];
    const float* fc1_b = (const float*)d_in[7];
    const float* fc2_w = (const float*)d_in[8];
    const float* fc2_b = (const float*)d_in[9];
    float* out = (float*)d_out;

    int n = in_sizes[0];          // 401408
    int E = in_sizes[1] / 2;      // 3211264

    k_init<<<1568, 256>>>(ei, n);
    k_count<<<(E + 255) / 256, 256>>>(ei, E);
    k_dinv<<<(n + 255) / 256, 256>>>(n);
    k_l1<<<(n + 255) / 256, 256>>>(x, W1, b1, n);
    k_l2<<<dim3(784, 16), 256>>>(W2, b2);
    k_gemm<<<dim3(4, SPLITS), 256>>>(fc1_w);
    k_final<<<NGRAPH, 128>>>(fc1_b, fc2_w, fc2_b, out);
}

// round 6
// speedup vs baseline: 1.3739x; 1.0940x over previous
#include <cuda_runtime.h>
#include <cuda_bf16.h>

// Problem constants (fixed by the dataset)
#define NN     401408          // nodes
#define EE     3211264         // edges
#define CAP    40              // slots per node (indegree ~ Poisson(8))
#define OVF_CAP 65536
#define KTOT   50176           // 784*64
#define NGRAPH 512
#define SPLITS 74              // split-K partitions (uneven: first 28 get 43 tiles)
#define GBK    16

typedef unsigned long long u64;

// ---------------- device scratch (static, no allocations) ----------------
__device__ int   g_cnt[NN];
__device__ float g_dinv[NN];
__device__ float g_xd[NN];                                     // x*dinv
__device__ int   g_slots[(size_t)CAP * NN];                    // slot-major
__device__ __align__(16) float g_h1[(size_t)NN * 32];          // PRESCALED by dinv
__device__ __align__(16) float g_h2t[(size_t)KTOT * NGRAPH];   // A^T: [k][g]
__device__ __align__(16) float g_part[(size_t)SPLITS * NGRAPH * 128];
__device__ int   g_ovf_n;
__device__ int   g_is64;
__device__ int   g_ovf_src[OVF_CAP];
__device__ int   g_ovf_dst[OVF_CAP];

// ---------------- ptx helpers ----------------
__device__ __forceinline__ u64 pack2(float lo, float hi) {
    u64 r; asm("mov.b64 %0, {%1, %2};" : "=l"(r) : "f"(lo), "f"(hi)); return r;
}
__device__ __forceinline__ float2 unpack2(u64 v) {
    float2 f; asm("mov.b64 {%0, %1}, %2;" : "=f"(f.x), "=f"(f.y) : "l"(v)); return f;
}
__device__ __forceinline__ void ffma2(u64& d, u64 a, u64 b) {
    asm("fma.rn.f32x2 %0, %1, %2, %0;" : "+l"(d) : "l"(a), "l"(b));
}
__device__ __forceinline__ void cp16(void* smem, const void* g) {
    unsigned sa = (unsigned)__cvta_generic_to_shared(smem);
    asm volatile("cp.async.cg.shared.global [%0], [%1], 16;" :: "r"(sa), "l"(g));
}
#define CP_COMMIT() asm volatile("cp.async.commit_group;")
#define CP_WAIT(n)  asm volatile("cp.async.wait_group %0;" :: "n"(n))

// ---------------- kernels ----------------

// Zero counts + detect edge_index dtype (int64 low/high word pattern).
__global__ void k_init(const int* __restrict__ ei, int n) {
    if (blockIdx.x == 0 && threadIdx.x == 0) {
        g_ovf_n = 0;
        int ok = 1;
        for (int i = 0; i < 64; i++)
            if (ei[2 * i + 1] != 0) { ok = 0; break; }
        g_is64 = ok;
    }
    for (int i = blockIdx.x * blockDim.x + threadIdx.x; i < n;
         i += gridDim.x * blockDim.x)
        g_cnt[i] = 0;
}

// Count in-degree and fill slot-major per-node slot table with sources.
__global__ void k_count(const int* __restrict__ ei, int E) {
    int e = blockIdx.x * blockDim.x + threadIdx.x;
    if (e >= E) return;
    int s, d;
    if (g_is64) {
        const int2* p = (const int2*)ei;
        s = p[e].x;
        d = p[(size_t)E + e].x;
    } else {
        s = ei[e];
        d = ei[(size_t)E + e];
    }
    if ((unsigned)s >= (unsigned)NN || (unsigned)d >= (unsigned)NN) return;
    int c = atomicAdd(&g_cnt[d], 1);
    if (c < CAP) {
        g_slots[(size_t)c * NN + d] = s;
    } else {
        int o = atomicAdd(&g_ovf_n, 1);
        if (o < OVF_CAP) { g_ovf_src[o] = s; g_ovf_dst[o] = d; }
    }
}

__global__ void k_dinv(const float* __restrict__ x, int n) {
    int i = blockIdx.x * blockDim.x + threadIdx.x;
    if (i < n) {
        float di = rsqrtf(1.0f + (float)g_cnt[i]);
        g_dinv[i] = di;
        g_xd[i] = x[i] * di;
    }
}

// Fused layer-1: scalar aggregate (single xd gather, MLP=4) + expand to 32 feats.
// Output h1 is PRESCALED by dinv[i].
__global__ void k_l1(const float* __restrict__ W1,
                     const float* __restrict__ b1, int n) {
    __shared__ float w[32], b[32];
    if (threadIdx.x < 32) { w[threadIdx.x] = W1[threadIdx.x]; b[threadIdx.x] = b1[threadIdx.x]; }
    __syncthreads();
    int i = blockIdx.x * blockDim.x + threadIdx.x;
    if (i >= n) return;
    int c = g_cnt[i];
    int m = c < CAP ? c : CAP;
    float sum = 0.f;
    int j = 0;
    for (; j + 4 <= m; j += 4) {
        int s0 = g_slots[(size_t)(j + 0) * NN + i];
        int s1 = g_slots[(size_t)(j + 1) * NN + i];
        int s2 = g_slots[(size_t)(j + 2) * NN + i];
        int s3 = g_slots[(size_t)(j + 3) * NN + i];
        float v0 = g_xd[s0], v1 = g_xd[s1], v2 = g_xd[s2], v3 = g_xd[s3];
        sum += (v0 + v1) + (v2 + v3);
    }
    for (; j < m; j++) sum += g_xd[g_slots[(size_t)j * NN + i]];
    if (c > CAP) {   // exactness path; essentially never taken
        int on = g_ovf_n; if (on > OVF_CAP) on = OVF_CAP;
        for (int e = 0; e < on; e++)
            if (g_ovf_dst[e] == i) sum += g_xd[g_ovf_src[e]];
    }
    float di = g_dinv[i];
    float tt = di * sum + g_xd[i] * di;
    float4* dst = (float4*)(g_h1 + (size_t)i * 32);
#pragma unroll
    for (int q = 0; q < 8; q++) {
        int f = q * 4;
        float4 r;
        r.x = fmaxf(tt * w[f + 0] + b[f + 0], 0.f) * di;
        r.y = fmaxf(tt * w[f + 1] + b[f + 1], 0.f) * di;
        r.z = fmaxf(tt * w[f + 2] + b[f + 2], 0.f) * di;
        r.w = fmaxf(tt * w[f + 3] + b[f + 3], 0.f) * di;
        dst[q] = r;
    }
}

// Layer-2: block = 32 nodes (fixed p, consecutive graphs g). Warp per 4 nodes.
// h1 is prescaled, so agg = plain sum; u = di*(acc + h1s[i]).
// W2 matmul uses packed f32x2 FMA (lane owns output pair lane/lane+32).
__global__ void __launch_bounds__(256) k_l2(const float* __restrict__ W2,
                                            const float* __restrict__ b2) {
    __shared__ u64  w2p[32 * 32];   // [f][lane] -> (W2[f,lane], W2[f,lane+32])
    __shared__ float h2t[32][65];   // [g_local][feat], padded
    __shared__ float b2s[64];
    int t = threadIdx.x;
    for (int idx = t; idx < 1024; idx += 256) {
        int f = idx >> 5, l = idx & 31;
        w2p[idx] = pack2(W2[f * 64 + l], W2[f * 64 + l + 32]);
    }
    if (t < 64) b2s[t] = b2[t];
    __syncthreads();

    int warp = t >> 5, lane = t & 31;
    int p = blockIdx.x;          // 0..783 node-in-graph
    int gblk = blockIdx.y;       // 0..15 graph block

#pragma unroll 1
    for (int q = 0; q < 4; q++) {
        int gl = warp * 4 + q;
        int i = (gblk * 32 + gl) * 784 + p;
        float di = g_dinv[i];
        int c = g_cnt[i];
        int m = c < CAP ? c : CAP;
        float acc = 0.f;
        int j = 0;
        for (; j + 4 <= m; j += 4) {
            int s0 = g_slots[(size_t)(j + 0) * NN + i];
            int s1 = g_slots[(size_t)(j + 1) * NN + i];
            int s2 = g_slots[(size_t)(j + 2) * NN + i];
            int s3 = g_slots[(size_t)(j + 3) * NN + i];
            float v0 = g_h1[(size_t)s0 * 32 + lane];
            float v1 = g_h1[(size_t)s1 * 32 + lane];
            float v2 = g_h1[(size_t)s2 * 32 + lane];
            float v3 = g_h1[(size_t)s3 * 32 + lane];
            acc += (v0 + v1) + (v2 + v3);
        }
        for (; j < m; j++)
            acc += g_h1[(size_t)g_slots[(size_t)j * NN + i] * 32 + lane];
        if (c > CAP) {
            int on = g_ovf_n; if (on > OVF_CAP) on = OVF_CAP;
            for (int e = 0; e < on; e++)
                if (g_ovf_dst[e] == i)
                    acc += g_h1[(size_t)g_ovf_src[e] * 32 + lane];
        }
        float u = di * (acc + g_h1[(size_t)i * 32 + lane]);

        u64 o = pack2(b2s[lane], b2s[lane + 32]);
#pragma unroll
        for (int f = 0; f < 32; f++) {
            float uf = __shfl_sync(0xffffffffu, u, f);
            ffma2(o, pack2(uf, uf), w2p[f * 32 + lane]);
        }
        float2 ov = unpack2(o);
        h2t[gl][lane]      = fmaxf(ov.x, 0.f);
        h2t[gl][lane + 32] = fmaxf(ov.y, 0.f);
    }
    __syncthreads();
    // transposed write-out: row = feature k = p*64+f, 32 consecutive g
    for (int idx = t; idx < 2048; idx += 256) {
        int f = idx >> 5, gl = idx & 31;
        g_h2t[(size_t)(p * 64 + f) * NGRAPH + gblk * 32 + gl] = h2t[gl][f];
    }
}

// Split-K fp32 GEMM with packed f32x2 FMA + cp.async double buffering.
// C[512x128] = A^T (g_h2t[k][g]) x B (fc1_w[k][j]).
// grid = (4 M-tiles of 128 graphs, 74 K-splits) = 296 blocks = 2/SM.
__global__ void __launch_bounds__(256) k_gemm(const float* __restrict__ B) {
    __shared__ __align__(16) float As[2][GBK * 128];   // [kk][g]
    __shared__ __align__(16) float Bs[2][GBK * 128];   // [kk][j]
    const int t = threadIdx.x;
    const int warp = t >> 5, lane = t & 31;
    const int g0 = blockIdx.x * 128;
    const int sp = blockIdx.y;
    const int t0 = sp * 42 + (sp < 28 ? sp : 28);
    const int nt = 42 + (sp < 28 ? 1 : 0);

    u64 acc[8][4];
#pragma unroll
    for (int i = 0; i < 8; i++)
#pragma unroll
        for (int j = 0; j < 4; j++) acc[i][j] = 0ull;

    const int r0 = t >> 5,         s0 = t & 31;
    const int r1 = (t + 256) >> 5, s1 = (t + 256) & 31;

#pragma unroll 1
    for (int tile = 0; tile < nt; tile++) {
        if (tile == 0) {
            int k0 = t0 * GBK;
            cp16(&As[0][r0 * 128 + s0 * 4], g_h2t + (size_t)(k0 + r0) * NGRAPH + g0 + s0 * 4);
            cp16(&As[0][r1 * 128 + s1 * 4], g_h2t + (size_t)(k0 + r1) * NGRAPH + g0 + s1 * 4);
            cp16(&Bs[0][r0 * 128 + s0 * 4], B + (size_t)(k0 + r0) * 128 + s0 * 4);
            cp16(&Bs[0][r1 * 128 + s1 * 4], B + (size_t)(k0 + r1) * 128 + s1 * 4);
            CP_COMMIT();
        }
        if (tile + 1 < nt) {
            int k0 = (t0 + tile + 1) * GBK;
            int nb = (tile + 1) & 1;
            cp16(&As[nb][r0 * 128 + s0 * 4], g_h2t + (size_t)(k0 + r0) * NGRAPH + g0 + s0 * 4);
            cp16(&As[nb][r1 * 128 + s1 * 4], g_h2t + (size_t)(k0 + r1) * NGRAPH + g0 + s1 * 4);
            cp16(&Bs[nb][r0 * 128 + s0 * 4], B + (size_t)(k0 + r0) * 128 + s0 * 4);
            cp16(&Bs[nb][r1 * 128 + s1 * 4], B + (size_t)(k0 + r1) * 128 + s1 * 4);
            CP_COMMIT();
            CP_WAIT(1);
        } else {
            CP_WAIT(0);
        }
        __syncthreads();

        const int buf = tile & 1;
#pragma unroll
        for (int kk = 0; kk < GBK; kk++) {
            float4 bv = *(const float4*)&Bs[buf][kk * 128 + lane * 4];
            u64 bp0 = pack2(bv.x, bv.x);
            u64 bp1 = pack2(bv.y, bv.y);
            u64 bp2 = pack2(bv.z, bv.z);
            u64 bp3 = pack2(bv.w, bv.w);
            const float* ar = &As[buf][kk * 128 + (warp << 4)];
#pragma unroll
            for (int rp = 0; rp < 8; rp++) {
                u64 ap = *(const u64*)(ar + 2 * rp);
                ffma2(acc[rp][0], ap, bp0);
                ffma2(acc[rp][1], ap, bp1);
                ffma2(acc[rp][2], ap, bp2);
                ffma2(acc[rp][3], ap, bp3);
            }
        }
        __syncthreads();
    }

#pragma unroll
    for (int rp = 0; rp < 8; rp++) {
        int grow = g0 + (warp << 4) + 2 * rp;
        float2 c0 = unpack2(acc[rp][0]);
        float2 c1 = unpack2(acc[rp][1]);
        float2 c2 = unpack2(acc[rp][2]);
        float2 c3 = unpack2(acc[rp][3]);
        float4 lo = make_float4(c0.x, c1.x, c2.x, c3.x);
        float4 hi = make_float4(c0.y, c1.y, c2.y, c3.y);
        *(float4*)&g_part[((size_t)sp * NGRAPH + grow)     * 128 + lane * 4] = lo;
        *(float4*)&g_part[((size_t)sp * NGRAPH + grow + 1) * 128 + lane * 4] = hi;
    }
}

// Reduce partials + fc1 bias + relu + fc2
__global__ void k_final(const float* __restrict__ fc1_b,
                        const float* __restrict__ fc2_w,
                        const float* __restrict__ fc2_b,
                        float* __restrict__ out) {
    int g = blockIdx.x;     // 512
    int j = threadIdx.x;    // 128
    float v = fc1_b[j];
#pragma unroll 2
    for (int s = 0; s < SPLITS; s++)
        v += g_part[((size_t)s * NGRAPH + g) * 128 + j];
    v = fmaxf(v, 0.f);
    __shared__ float f1[128];
    f1[j] = v;
    __syncthreads();
    if (j < 10) {
        float o = fc2_b[j];
#pragma unroll 16
        for (int tt = 0; tt < 128; tt++) o += f1[tt] * fc2_w[tt * 10 + j];
        out[g * 10 + j] = o;
    }
}

// ---------------- host launcher ----------------
extern "C" void kernel_launch(void* const* d_in, const int* in_sizes, int n_in,
                              void* d_out, int out_size) {
    const float* x     = (const float*)d_in[0];
    const int*   ei    = (const int*)d_in[1];     // int32 OR int64 (auto-detected)
    const float* W1    = (const float*)d_in[2];
    const float* b1    = (const float*)d_in[3];
    const float* W2    = (const float*)d_in[4];
    const float* b2    = (const float*)d_in[5];
    const float* fc1_w = (const float*)d_in[6];
    const float* fc1_b = (const float*)d_in[7];
    const float* fc2_w = (const float*)d_in[8];
    const float* fc2_b = (const float*)d_in[9];
    float* out = (float*)d_out;

    int n = in_sizes[0];          // 401408
    int E = in_sizes[1] / 2;      // 3211264

    k_init<<<1568, 256>>>(ei, n);
    k_count<<<(E + 255) / 256, 256>>>(ei, E);
    k_dinv<<<(n + 255) / 256, 256>>>(x, n);
    k_l1<<<(n + 255) / 256, 256>>>(W1, b1, n);
    k_l2<<<dim3(784, 16), 256>>>(W2, b2);
    k_gemm<<<dim3(4, SPLITS), 256>>>(fc1_w);
    k_final<<<NGRAPH, 128>>>(fc1_b, fc2_w, fc2_b, out);
}

// round 8
// speedup vs baseline: 1.4523x; 1.0571x over previous
#include <cuda_runtime.h>
#include <cuda_bf16.h>
#include <cstdint>

// Problem constants (fixed by the dataset)
#define NN     401408          // nodes
#define EE     3211264         // edges
#define CAP    40              // slots per node (indegree ~ Poisson(8))
#define OVF_CAP 65536
#define KTOT   50176           // 784*64
#define NGRAPH 512
#define SPLITS 37              // split-K partitions over 1568 K-chunks of 32

typedef unsigned long long u64;

// ---------------- device scratch (static, no allocations) ----------------
__device__ int   g_cnt[NN];
__device__ float g_dinv[NN];
__device__ float g_xd[NN];                                     // x*dinv
__device__ int   g_slots[(size_t)CAP * NN];                    // slot-major
__device__ __align__(16) float g_h1[(size_t)NN * 32];          // PRESCALED by dinv
__device__ __align__(16) __nv_bfloat16 g_h2h[(size_t)NGRAPH * KTOT];  // A hi  [g][k]
__device__ __align__(16) __nv_bfloat16 g_h2l[(size_t)NGRAPH * KTOT];  // A lo  [g][k]
__device__ __align__(16) __nv_bfloat16 g_fc1h[(size_t)128 * KTOT];    // B^T hi [n][k]
__device__ __align__(16) __nv_bfloat16 g_fc1l[(size_t)128 * KTOT];    // B^T lo [n][k]
__device__ __align__(16) float g_part[(size_t)SPLITS * NGRAPH * 128];
__device__ int   g_ovf_n;
__device__ int   g_is64;
__device__ int   g_ovf_src[OVF_CAP];
__device__ int   g_ovf_dst[OVF_CAP];

// ---------------- ptx helpers ----------------
__device__ __forceinline__ u64 pack2(float lo, float hi) {
    u64 r; asm("mov.b64 %0, {%1, %2};" : "=l"(r) : "f"(lo), "f"(hi)); return r;
}
__device__ __forceinline__ float2 unpack2(u64 v) {
    float2 f; asm("mov.b64 {%0, %1}, %2;" : "=f"(f.x), "=f"(f.y) : "l"(v)); return f;
}
__device__ __forceinline__ void ffma2(u64& d, u64 a, u64 b) {
    asm("fma.rn.f32x2 %0, %1, %2, %0;" : "+l"(d) : "l"(a), "l"(b));
}
__device__ __forceinline__ void cp16s(uint32_t sa, const void* g) {
    asm volatile("cp.async.cg.shared.global [%0], [%1], 16;" :: "r"(sa), "l"(g));
}
#define CP_COMMIT() asm volatile("cp.async.commit_group;")
#define CP_WAIT(n)  asm volatile("cp.async.wait_group %0;" :: "n"(n))

__device__ __forceinline__ uint32_t smem_u32(const void* p) {
    uint32_t a;
    asm("{ .reg .u64 t; cvta.to.shared.u64 t, %1; cvt.u32.u64 %0, t; }" : "=r"(a) : "l"(p));
    return a;
}
__device__ __forceinline__ void ldsm4(uint32_t* r, uint32_t a) {
    asm volatile("ldmatrix.sync.aligned.m8n8.x4.shared.b16 {%0,%1,%2,%3}, [%4];"
                 : "=r"(r[0]), "=r"(r[1]), "=r"(r[2]), "=r"(r[3]) : "r"(a));
}
__device__ __forceinline__ void mma_bf16(float* c, const uint32_t* a, const uint32_t* b) {
    asm volatile(
        "mma.sync.aligned.m16n8k16.row.col.f32.bf16.bf16.f32 "
        "{%0,%1,%2,%3}, {%4,%5,%6,%7}, {%8,%9}, {%0,%1,%2,%3};"
        : "+f"(c[0]), "+f"(c[1]), "+f"(c[2]), "+f"(c[3])
        : "r"(a[0]), "r"(a[1]), "r"(a[2]), "r"(a[3]), "r"(b[0]), "r"(b[1]));
}
__device__ __forceinline__ void split_bf16(float v, __nv_bfloat16& h, __nv_bfloat16& l) {
    h = __float2bfloat16_rn(v);
    l = __float2bfloat16_rn(v - __bfloat162float(h));
}

// ---------------- kernels ----------------

// Zero counts + detect edge_index dtype (int64 low/high word pattern).
__global__ void k_init(const int* __restrict__ ei, int n) {
    if (blockIdx.x == 0 && threadIdx.x == 0) {
        g_ovf_n = 0;
        int ok = 1;
        for (int i = 0; i < 64; i++)
            if (ei[2 * i + 1] != 0) { ok = 0; break; }
        g_is64 = ok;
    }
    for (int i = blockIdx.x * blockDim.x + threadIdx.x; i < n;
         i += gridDim.x * blockDim.x)
        g_cnt[i] = 0;
}

// Count in-degree and fill slot-major per-node slot table with sources.
__global__ void k_count(const int* __restrict__ ei, int E) {
    int e = blockIdx.x * blockDim.x + threadIdx.x;
    if (e >= E) return;
    int s, d;
    if (g_is64) {
        const int2* p = (const int2*)ei;
        s = p[e].x;
        d = p[(size_t)E + e].x;
    } else {
        s = ei[e];
        d = ei[(size_t)E + e];
    }
    if ((unsigned)s >= (unsigned)NN || (unsigned)d >= (unsigned)NN) return;
    int c = atomicAdd(&g_cnt[d], 1);
    if (c < CAP) {
        g_slots[(size_t)c * NN + d] = s;
    } else {
        int o = atomicAdd(&g_ovf_n, 1);
        if (o < OVF_CAP) { g_ovf_src[o] = s; g_ovf_dst[o] = d; }
    }
}

__global__ void k_dinv(const float* __restrict__ x, int n) {
    int i = blockIdx.x * blockDim.x + threadIdx.x;
    if (i < n) {
        float di = rsqrtf(1.0f + (float)g_cnt[i]);
        g_dinv[i] = di;
        g_xd[i] = x[i] * di;
    }
}

// Fused layer-1: scalar aggregate (xd gather, index-prefetch MLP=8) + expand.
// Output h1 PRESCALED by dinv[i].
__global__ void k_l1(const float* __restrict__ W1,
                     const float* __restrict__ b1, int n) {
    __shared__ float w[32], b[32];
    if (threadIdx.x < 32) { w[threadIdx.x] = W1[threadIdx.x]; b[threadIdx.x] = b1[threadIdx.x]; }
    __syncthreads();
    int i = blockIdx.x * blockDim.x + threadIdx.x;
    if (i >= n) return;
    int c = g_cnt[i];
    int m = c < CAP ? c : CAP;
    float sum = 0.f;
    int j = 0;
    for (; j + 8 <= m; j += 8) {
        int ss[8];
#pragma unroll
        for (int q = 0; q < 8; q++) ss[q] = g_slots[(size_t)(j + q) * NN + i];
        float v[8];
#pragma unroll
        for (int q = 0; q < 8; q++) v[q] = g_xd[ss[q]];
        sum += ((v[0] + v[1]) + (v[2] + v[3])) + ((v[4] + v[5]) + (v[6] + v[7]));
    }
    for (; j + 4 <= m; j += 4) {
        int s0 = g_slots[(size_t)(j + 0) * NN + i];
        int s1 = g_slots[(size_t)(j + 1) * NN + i];
        int s2 = g_slots[(size_t)(j + 2) * NN + i];
        int s3 = g_slots[(size_t)(j + 3) * NN + i];
        sum += (g_xd[s0] + g_xd[s1]) + (g_xd[s2] + g_xd[s3]);
    }
    for (; j < m; j++) sum += g_xd[g_slots[(size_t)j * NN + i]];
    if (c > CAP) {   // exactness path; essentially never taken
        int on = g_ovf_n; if (on > OVF_CAP) on = OVF_CAP;
        for (int e = 0; e < on; e++)
            if (g_ovf_dst[e] == i) sum += g_xd[g_ovf_src[e]];
    }
    float di = g_dinv[i];
    float tt = di * sum + g_xd[i] * di;
    float4* dst = (float4*)(g_h1 + (size_t)i * 32);
#pragma unroll
    for (int q = 0; q < 8; q++) {
        int f = q * 4;
        float4 r;
        r.x = fmaxf(tt * w[f + 0] + b[f + 0], 0.f) * di;
        r.y = fmaxf(tt * w[f + 1] + b[f + 1], 0.f) * di;
        r.z = fmaxf(tt * w[f + 2] + b[f + 2], 0.f) * di;
        r.w = fmaxf(tt * w[f + 3] + b[f + 3], 0.f) * di;
        dst[q] = r;
    }
}

// Transpose + bf16-split fc1_w [k][n] -> g_fc1h/g_fc1l [n][k]
__global__ void __launch_bounds__(256) k_cvtB(const float* __restrict__ B) {
    __shared__ float tile[32][129];
    int k0 = blockIdx.x * 32;
    int t = threadIdx.x;
    for (int idx = t; idx < 4096; idx += 256) {
        int kr = idx >> 7, nn = idx & 127;
        tile[kr][nn] = B[(size_t)(k0 + kr) * 128 + nn];
    }
    __syncthreads();
    int n = t >> 1, ks = (t & 1) * 16;
    uint32_t ph[8], pl[8];
#pragma unroll
    for (int q = 0; q < 8; q++) {
        __nv_bfloat16 h0, l0, h1, l1;
        split_bf16(tile[ks + 2 * q][n], h0, l0);
        split_bf16(tile[ks + 2 * q + 1][n], h1, l1);
        ph[q] = (uint32_t)__bfloat16_as_ushort(h0) | ((uint32_t)__bfloat16_as_ushort(h1) << 16);
        pl[q] = (uint32_t)__bfloat16_as_ushort(l0) | ((uint32_t)__bfloat16_as_ushort(l1) << 16);
    }
    size_t o = (size_t)n * KTOT + k0 + ks;
    *(uint4*)(g_fc1h + o)     = make_uint4(ph[0], ph[1], ph[2], ph[3]);
    *(uint4*)(g_fc1h + o + 8) = make_uint4(ph[4], ph[5], ph[6], ph[7]);
    *(uint4*)(g_fc1l + o)     = make_uint4(pl[0], pl[1], pl[2], pl[3]);
    *(uint4*)(g_fc1l + o + 8) = make_uint4(pl[4], pl[5], pl[6], pl[7]);
}

// Layer-2: block = 32 graphs at fixed p. Gather-agg (MLP=8) + W2 FFMA2 matmul,
// epilogue emits bf16 hi/lo rows [g][k].
__global__ void __launch_bounds__(256) k_l2(const float* __restrict__ W2,
                                            const float* __restrict__ b2) {
    __shared__ u64  w2p[32 * 32];   // [f][lane] -> (W2[f,lane], W2[f,lane+32])
    __shared__ float h2t[32][65];   // [g_local][feat], padded
    __shared__ float b2s[64];
    int t = threadIdx.x;
    for (int idx = t; idx < 1024; idx += 256) {
        int f = idx >> 5, l = idx & 31;
        w2p[idx] = pack2(W2[f * 64 + l], W2[f * 64 + l + 32]);
    }
    if (t < 64) b2s[t] = b2[t];
    __syncthreads();

    int warp = t >> 5, lane = t & 31;
    int p = blockIdx.x;          // 0..783 node-in-graph
    int gblk = blockIdx.y;       // 0..15 graph block

#pragma unroll 1
    for (int q = 0; q < 4; q++) {
        int gl = warp * 4 + q;
        int i = (gblk * 32 + gl) * 784 + p;
        float di = g_dinv[i];
        int c = g_cnt[i];
        int m = c < CAP ? c : CAP;
        float acc = 0.f;
        int j = 0;
        for (; j + 8 <= m; j += 8) {
            int ss[8];
#pragma unroll
            for (int qq = 0; qq < 8; qq++) ss[qq] = g_slots[(size_t)(j + qq) * NN + i];
            float v[8];
#pragma unroll
            for (int qq = 0; qq < 8; qq++) v[qq] = g_h1[(size_t)ss[qq] * 32 + lane];
            acc += ((v[0] + v[1]) + (v[2] + v[3])) + ((v[4] + v[5]) + (v[6] + v[7]));
        }
        for (; j + 4 <= m; j += 4) {
            int s0 = g_slots[(size_t)(j + 0) * NN + i];
            int s1 = g_slots[(size_t)(j + 1) * NN + i];
            int s2 = g_slots[(size_t)(j + 2) * NN + i];
            int s3 = g_slots[(size_t)(j + 3) * NN + i];
            float v0 = g_h1[(size_t)s0 * 32 + lane];
            float v1 = g_h1[(size_t)s1 * 32 + lane];
            float v2 = g_h1[(size_t)s2 * 32 + lane];
            float v3 = g_h1[(size_t)s3 * 32 + lane];
            acc += (v0 + v1) + (v2 + v3);
        }
        for (; j < m; j++)
            acc += g_h1[(size_t)g_slots[(size_t)j * NN + i] * 32 + lane];
        if (c > CAP) {
            int on = g_ovf_n; if (on > OVF_CAP) on = OVF_CAP;
            for (int e = 0; e < on; e++)
                if (g_ovf_dst[e] == i)
                    acc += g_h1[(size_t)g_ovf_src[e] * 32 + lane];
        }
        float u = di * (acc + g_h1[(size_t)i * 32 + lane]);

        u64 o0 = pack2(b2s[lane], b2s[lane + 32]);
        u64 o1 = 0ull;
#pragma unroll
        for (int f = 0; f < 32; f += 2) {
            float uf0 = __shfl_sync(0xffffffffu, u, f);
            float uf1 = __shfl_sync(0xffffffffu, u, f + 1);
            ffma2(o0, pack2(uf0, uf0), w2p[f * 32 + lane]);
            ffma2(o1, pack2(uf1, uf1), w2p[(f + 1) * 32 + lane]);
        }
        float2 a0 = unpack2(o0), a1 = unpack2(o1);
        h2t[gl][lane]      = fmaxf(a0.x + a1.x, 0.f);
        h2t[gl][lane + 32] = fmaxf(a0.y + a1.y, 0.f);
    }
    __syncthreads();
    // epilogue: bf16 hi/lo write-out, rows [g][p*64 + f]
    for (int idx = t; idx < 512; idx += 256) {
        int gl = idx >> 4, f4 = (idx & 15) * 4;
        uint32_t ph[2], pl[2];
#pragma unroll
        for (int q = 0; q < 2; q++) {
            __nv_bfloat16 h0, l0, h1, l1;
            split_bf16(h2t[gl][f4 + 2 * q], h0, l0);
            split_bf16(h2t[gl][f4 + 2 * q + 1], h1, l1);
            ph[q] = (uint32_t)__bfloat16_as_ushort(h0) | ((uint32_t)__bfloat16_as_ushort(h1) << 16);
            pl[q] = (uint32_t)__bfloat16_as_ushort(l0) | ((uint32_t)__bfloat16_as_ushort(l1) << 16);
        }
        size_t o = (size_t)(gblk * 32 + gl) * KTOT + p * 64 + f4;
        *(uint2*)(g_h2h + o) = make_uint2(ph[0], ph[1]);
        *(uint2*)(g_h2l + o) = make_uint2(pl[0], pl[1]);
    }
}

// HMMA bf16-split GEMM (mma.sync m16n8k16): C[512x128] = A[512xK] B[Kx128],
// C ≈ Ah·Bh + Ah·Bl + Al·Bh, fp32 accumulate. Split-K over 37 partitions of
// K-chunks (32 bf16). grid (4 M-tiles, 37) = 148 CTAs, 256 thr (8 warps, 4Mx2N).
// smem rows: 32 bf16 = 64B data in 80B stride (bank-conflict-free ldmatrix).
#define HG_BUF 40960     // bytes per double-buffer half (4 arrays x 128 rows x 80B)
__global__ void __launch_bounds__(256) k_hgemm() {
    extern __shared__ __align__(16) char sm[];
    const int t = threadIdx.x;
    const int warp = t >> 5, lane = t & 31;
    const int warpM = warp & 3, warpN = warp >> 2;
    const int g0 = blockIdx.x * 128;
    const int sp = blockIdx.y;
    const int t0 = sp * 42 + (sp < 14 ? sp : 14);
    const int ntc = 42 + (sp < 14 ? 1 : 0);

    const uint32_t sb = smem_u32(sm);

    float C[2][8][4];
#pragma unroll
    for (int a = 0; a < 2; a++)
#pragma unroll
        for (int bq = 0; bq < 8; bq++)
#pragma unroll
            for (int cq = 0; cq < 4; cq++) C[a][bq][cq] = 0.f;

    // per-chunk loader: Ah|Al|Bh|Bl, each 128 rows x 64B (80B stride)
    auto load_chunk = [&](int ch, int buf) {
        const size_t kb = (size_t)(t0 + ch) * 32;
        const uint32_t base = sb + buf * HG_BUF;
#pragma unroll
        for (int i = 0; i < 8; i++) {
            int v = t + i * 256;
            int arr = v >> 9, rem = v & 511;
            int row = rem >> 2, c16 = rem & 3;
            uint32_t dst = base + arr * 10240 + row * 80 + c16 * 16;
            const __nv_bfloat16* src;
            if (arr == 0)      src = g_h2h  + (size_t)(g0 + row) * KTOT + kb + c16 * 8;
            else if (arr == 1) src = g_h2l  + (size_t)(g0 + row) * KTOT + kb + c16 * 8;
            else if (arr == 2) src = g_fc1h + (size_t)row * KTOT + kb + c16 * 8;
            else               src = g_fc1l + (size_t)row * KTOT + kb + c16 * 8;
            cp16s(dst, src);
        }
        CP_COMMIT();
    };

    load_chunk(0, 0);

#pragma unroll 1
    for (int ch = 0; ch < ntc; ch++) {
        if (ch + 1 < ntc) {
            load_chunk(ch + 1, (ch + 1) & 1);
            CP_WAIT(1);
        } else {
            CP_WAIT(0);
        }
        __syncthreads();

        const uint32_t bufB = sb + (ch & 1) * HG_BUF;
#pragma unroll
        for (int k16 = 0; k16 < 2; k16++) {
            const uint32_t kOff = (k16 * 16 + ((lane >> 4) << 3)) * 2;
            // A fragments (hi, lo) for 2 m-tiles
            uint32_t ah[2][4], al[2][4];
#pragma unroll
            for (int mt = 0; mt < 2; mt++) {
                uint32_t rowo = (warpM * 32 + mt * 16 + (lane & 15)) * 80 + kOff;
                ldsm4(ah[mt], bufB + rowo);
                ldsm4(al[mt], bufB + 10240 + rowo);
            }
            // B fragments (hi, lo) for 8 n-tiles (x4 covers 2 n-tiles)
            uint32_t bh[8][2], bl[8][2];
#pragma unroll
            for (int ntp = 0; ntp < 4; ntp++) {
                uint32_t rowo = (warpN * 64 + ntp * 16 + (lane & 15)) * 80 + kOff;
                uint32_t q[4];
                ldsm4(q, bufB + 20480 + rowo);
                bh[2 * ntp][0] = q[0]; bh[2 * ntp][1] = q[2];
                bh[2 * ntp + 1][0] = q[1]; bh[2 * ntp + 1][1] = q[3];
                ldsm4(q, bufB + 30720 + rowo);
                bl[2 * ntp][0] = q[0]; bl[2 * ntp][1] = q[2];
                bl[2 * ntp + 1][0] = q[1]; bl[2 * ntp + 1][1] = q[3];
            }
#pragma unroll
            for (int mt = 0; mt < 2; mt++)
#pragma unroll
                for (int nt = 0; nt < 8; nt++) {
                    mma_bf16(C[mt][nt], ah[mt], bh[nt]);
                    mma_bf16(C[mt][nt], ah[mt], bl[nt]);
                    mma_bf16(C[mt][nt], al[mt], bh[nt]);
                }
        }
        __syncthreads();
    }

    // epilogue: per-thread float2 writes to split partials
#pragma unroll
    for (int mt = 0; mt < 2; mt++) {
        int r0 = g0 + warpM * 32 + mt * 16 + (lane >> 2);
#pragma unroll
        for (int nt = 0; nt < 8; nt++) {
            int col = warpN * 64 + nt * 8 + (lane & 3) * 2;
            float* d = &g_part[((size_t)sp * NGRAPH + r0) * 128 + col];
            *(float2*)d             = make_float2(C[mt][nt][0], C[mt][nt][1]);
            *(float2*)(d + 8 * 128) = make_float2(C[mt][nt][2], C[mt][nt][3]);
        }
    }
}

// Reduce partials + fc1 bias + relu + fc2
__global__ void k_final(const float* __restrict__ fc1_b,
                        const float* __restrict__ fc2_w,
                        const float* __restrict__ fc2_b,
                        float* __restrict__ out) {
    int g = blockIdx.x;     // 512
    int j = threadIdx.x;    // 128
    float v = fc1_b[j];
#pragma unroll 2
    for (int s = 0; s < SPLITS; s++)
        v += g_part[((size_t)s * NGRAPH + g) * 128 + j];
    v = fmaxf(v, 0.f);
    __shared__ float f1[128];
    f1[j] = v;
    __syncthreads();
    if (j < 10) {
        float o = fc2_b[j];
#pragma unroll 16
        for (int tt = 0; tt < 128; tt++) o += f1[tt] * fc2_w[tt * 10 + j];
        out[g * 10 + j] = o;
    }
}

// ---------------- host launcher ----------------
extern "C" void kernel_launch(void* const* d_in, const int* in_sizes, int n_in,
                              void* d_out, int out_size) {
    const float* x     = (const float*)d_in[0];
    const int*   ei    = (const int*)d_in[1];     // int32 OR int64 (auto-detected)
    const float* W1    = (const float*)d_in[2];
    const float* b1    = (const float*)d_in[3];
    const float* W2    = (const float*)d_in[4];
    const float* b2    = (const float*)d_in[5];
    const float* fc1_w = (const float*)d_in[6];
    const float* fc1_b = (const float*)d_in[7];
    const float* fc2_w = (const float*)d_in[8];
    const float* fc2_b = (const float*)d_in[9];
    float* out = (float*)d_out;

    int n = in_sizes[0];          // 401408
    int E = in_sizes[1] / 2;      // 3211264

    static int smem_set = 0;
    if (!smem_set) {
        cudaFuncSetAttribute(k_hgemm, cudaFuncAttributeMaxDynamicSharedMemorySize,
                             2 * HG_BUF);
        smem_set = 1;
    }

    k_init<<<1568, 256>>>(ei, n);
    k_count<<<(E + 255) / 256, 256>>>(ei, E);
    k_dinv<<<(n + 255) / 256, 256>>>(x, n);
    k_l1<<<(n + 255) / 256, 256>>>(W1, b1, n);
    k_cvtB<<<1568, 256>>>(fc1_w);
    k_l2<<<dim3(784, 16), 256>>>(W2, b2);
    k_hgemm<<<dim3(4, SPLITS), 256, 2 * HG_BUF>>>();
    k_final<<<NGRAPH, 128>>>(fc1_b, fc2_w, fc2_b, out);
}

// round 9
// speedup vs baseline: 2.1498x; 1.4802x over previous
#include <cuda_runtime.h>
#include <cuda_bf16.h>
#include <cstdint>

// Problem constants (fixed by the dataset)
#define NN     401408          // nodes
#define EE     3211264         // edges
#define CAP    40              // slots per node (indegree ~ Poisson(8))
#define OVF_CAP 65536
#define KTOT   50176           // 784*64
#define NGRAPH 512
#define SPLITS 37              // split-K partitions over 1568 K-chunks of 32

typedef unsigned long long u64;

// ---------------- device scratch (static, no allocations) ----------------
__device__ int   g_cnt[NN];
__device__ float g_dinv[NN];
__device__ float g_xd[NN];                                     // x*dinv
__device__ int   g_slots[(size_t)CAP * NN];                    // slot-major
__device__ __align__(16) float g_h1[(size_t)NN * 32];          // PRESCALED by dinv (fallback path)
__device__ __align__(8)  float2 g_ac[NN];                      // (relu(tt)*di, min(tt,0)*di)
__device__ float g_P[64], g_Q[64];
__device__ __align__(16) __nv_bfloat16 g_h2h[(size_t)NGRAPH * KTOT];  // A hi  [g][k]
__device__ __align__(16) __nv_bfloat16 g_h2l[(size_t)NGRAPH * KTOT];  // A lo  [g][k]
__device__ __align__(16) __nv_bfloat16 g_fc1h[(size_t)128 * KTOT];    // B^T hi [n][k]
__device__ __align__(16) __nv_bfloat16 g_fc1l[(size_t)128 * KTOT];    // B^T lo [n][k]
__device__ __align__(16) float g_part[(size_t)SPLITS * NGRAPH * 128];
__device__ int   g_ovf_n;
__device__ int   g_is64;
__device__ int   g_b1nz;
__device__ int   g_ovf_src[OVF_CAP];
__device__ int   g_ovf_dst[OVF_CAP];

// ---------------- ptx helpers ----------------
__device__ __forceinline__ u64 pack2(float lo, float hi) {
    u64 r; asm("mov.b64 %0, {%1, %2};" : "=l"(r) : "f"(lo), "f"(hi)); return r;
}
__device__ __forceinline__ float2 unpack2(u64 v) {
    float2 f; asm("mov.b64 {%0, %1}, %2;" : "=f"(f.x), "=f"(f.y) : "l"(v)); return f;
}
__device__ __forceinline__ void ffma2(u64& d, u64 a, u64 b) {
    asm("fma.rn.f32x2 %0, %1, %2, %0;" : "+l"(d) : "l"(a), "l"(b));
}
__device__ __forceinline__ void cp16s(uint32_t sa, const void* g) {
    asm volatile("cp.async.cg.shared.global [%0], [%1], 16;" :: "r"(sa), "l"(g));
}
#define CP_COMMIT() asm volatile("cp.async.commit_group;")
#define CP_WAIT(n)  asm volatile("cp.async.wait_group %0;" :: "n"(n))

__device__ __forceinline__ uint32_t smem_u32(const void* p) {
    uint32_t a;
    asm("{ .reg .u64 t; cvta.to.shared.u64 t, %1; cvt.u32.u64 %0, t; }" : "=r"(a) : "l"(p));
    return a;
}
__device__ __forceinline__ void ldsm4(uint32_t* r, uint32_t a) {
    asm volatile("ldmatrix.sync.aligned.m8n8.x4.shared.b16 {%0,%1,%2,%3}, [%4];"
                 : "=r"(r[0]), "=r"(r[1]), "=r"(r[2]), "=r"(r[3]) : "r"(a));
}
__device__ __forceinline__ void mma_bf16(float* c, const uint32_t* a, const uint32_t* b) {
    asm volatile(
        "mma.sync.aligned.m16n8k16.row.col.f32.bf16.bf16.f32 "
        "{%0,%1,%2,%3}, {%4,%5,%6,%7}, {%8,%9}, {%0,%1,%2,%3};"
        : "+f"(c[0]), "+f"(c[1]), "+f"(c[2]), "+f"(c[3])
        : "r"(a[0]), "r"(a[1]), "r"(a[2]), "r"(a[3]), "r"(b[0]), "r"(b[1]));
}
__device__ __forceinline__ void split_bf16(float v, __nv_bfloat16& h, __nv_bfloat16& l) {
    h = __float2bfloat16_rn(v);
    l = __float2bfloat16_rn(v - __bfloat162float(h));
}

// ---------------- kernels ----------------

// Zero counts + detect edge dtype + detect b1==0 (enables rank-2 fast path).
__global__ void k_init(const int* __restrict__ ei, const float* __restrict__ b1, int n) {
    if (blockIdx.x == 0 && threadIdx.x == 0) {
        g_ovf_n = 0;
        int ok = 1;
        for (int i = 0; i < 64; i++)
            if (ei[2 * i + 1] != 0) { ok = 0; break; }
        g_is64 = ok;
        int nz = 0;
        for (int f = 0; f < 32; f++)
            if (b1[f] != 0.0f) { nz = 1; break; }
        g_b1nz = nz;
    }
    for (int i = blockIdx.x * blockDim.x + threadIdx.x; i < n;
         i += gridDim.x * blockDim.x)
        g_cnt[i] = 0;
}

// Count in-degree and fill slot-major per-node slot table with sources.
__global__ void k_count(const int* __restrict__ ei, int E) {
    int e = blockIdx.x * blockDim.x + threadIdx.x;
    if (e >= E) return;
    int s, d;
    if (g_is64) {
        const int2* p = (const int2*)ei;
        s = p[e].x;
        d = p[(size_t)E + e].x;
    } else {
        s = ei[e];
        d = ei[(size_t)E + e];
    }
    if ((unsigned)s >= (unsigned)NN || (unsigned)d >= (unsigned)NN) return;
    int c = atomicAdd(&g_cnt[d], 1);
    if (c < CAP) {
        g_slots[(size_t)c * NN + d] = s;
    } else {
        int o = atomicAdd(&g_ovf_n, 1);
        if (o < OVF_CAP) { g_ovf_src[o] = s; g_ovf_dst[o] = d; }
    }
}

__global__ void k_dinv(const float* __restrict__ x, int n) {
    int i = blockIdx.x * blockDim.x + threadIdx.x;
    if (i < n) {
        float di = rsqrtf(1.0f + (float)g_cnt[i]);
        g_dinv[i] = di;
        g_xd[i] = x[i] * di;
    }
}

// P_j = sum_{w_f>0} W2[f,j]*w_f ; Q_j = sum_{w_f<0} W2[f,j]*w_f
__global__ void k_pq(const float* __restrict__ W1, const float* __restrict__ W2) {
    int j = threadIdx.x;   // 64
    float p = 0.f, q = 0.f;
    for (int f = 0; f < 32; f++) {
        float w = W1[f], v = W2[f * 64 + j];
        if (w > 0.f) p += v * w; else q += v * w;
    }
    g_P[j] = p; g_Q[j] = q;
}

// Fused layer-1: scalar aggregate (xd gather, MLP=8).
// Fast path (b1==0): store only (ap,an). Fallback: full 32-feat h1 expansion.
__global__ void k_l1(const float* __restrict__ W1,
                     const float* __restrict__ b1, int n) {
    __shared__ float w[32], b[32];
    if (threadIdx.x < 32) { w[threadIdx.x] = W1[threadIdx.x]; b[threadIdx.x] = b1[threadIdx.x]; }
    __syncthreads();
    int i = blockIdx.x * blockDim.x + threadIdx.x;
    if (i >= n) return;
    int c = g_cnt[i];
    int m = c < CAP ? c : CAP;
    float sum = 0.f;
    int j = 0;
    for (; j + 8 <= m; j += 8) {
        int ss[8];
#pragma unroll
        for (int q = 0; q < 8; q++) ss[q] = g_slots[(size_t)(j + q) * NN + i];
        float v[8];
#pragma unroll
        for (int q = 0; q < 8; q++) v[q] = g_xd[ss[q]];
        sum += ((v[0] + v[1]) + (v[2] + v[3])) + ((v[4] + v[5]) + (v[6] + v[7]));
    }
    for (; j + 4 <= m; j += 4) {
        int s0 = g_slots[(size_t)(j + 0) * NN + i];
        int s1 = g_slots[(size_t)(j + 1) * NN + i];
        int s2 = g_slots[(size_t)(j + 2) * NN + i];
        int s3 = g_slots[(size_t)(j + 3) * NN + i];
        sum += (g_xd[s0] + g_xd[s1]) + (g_xd[s2] + g_xd[s3]);
    }
    for (; j < m; j++) sum += g_xd[g_slots[(size_t)j * NN + i]];
    if (c > CAP) {   // exactness path; essentially never taken
        int on = g_ovf_n; if (on > OVF_CAP) on = OVF_CAP;
        for (int e = 0; e < on; e++)
            if (g_ovf_dst[e] == i) sum += g_xd[g_ovf_src[e]];
    }
    float di = g_dinv[i];
    float tt = di * sum + g_xd[i] * di;
    if (!g_b1nz) {
        g_ac[i] = make_float2(fmaxf(tt, 0.f) * di, fminf(tt, 0.f) * di);
        return;
    }
    float4* dst = (float4*)(g_h1 + (size_t)i * 32);
#pragma unroll
    for (int q = 0; q < 8; q++) {
        int f = q * 4;
        float4 r;
        r.x = fmaxf(tt * w[f + 0] + b[f + 0], 0.f) * di;
        r.y = fmaxf(tt * w[f + 1] + b[f + 1], 0.f) * di;
        r.z = fmaxf(tt * w[f + 2] + b[f + 2], 0.f) * di;
        r.w = fmaxf(tt * w[f + 3] + b[f + 3], 0.f) * di;
        dst[q] = r;
    }
}

// Transpose + bf16-split fc1_w [k][n] -> g_fc1h/g_fc1l [n][k]
__global__ void __launch_bounds__(256) k_cvtB(const float* __restrict__ B) {
    __shared__ float tile[32][129];
    int k0 = blockIdx.x * 32;
    int t = threadIdx.x;
    for (int idx = t; idx < 4096; idx += 256) {
        int kr = idx >> 7, nn = idx & 127;
        tile[kr][nn] = B[(size_t)(k0 + kr) * 128 + nn];
    }
    __syncthreads();
    int n = t >> 1, ks = (t & 1) * 16;
    uint32_t ph[8], pl[8];
#pragma unroll
    for (int q = 0; q < 8; q++) {
        __nv_bfloat16 h0, l0, h1, l1;
        split_bf16(tile[ks + 2 * q][n], h0, l0);
        split_bf16(tile[ks + 2 * q + 1][n], h1, l1);
        ph[q] = (uint32_t)__bfloat16_as_ushort(h0) | ((uint32_t)__bfloat16_as_ushort(h1) << 16);
        pl[q] = (uint32_t)__bfloat16_as_ushort(l0) | ((uint32_t)__bfloat16_as_ushort(l1) << 16);
    }
    size_t o = (size_t)n * KTOT + k0 + ks;
    *(uint4*)(g_fc1h + o)     = make_uint4(ph[0], ph[1], ph[2], ph[3]);
    *(uint4*)(g_fc1h + o + 8) = make_uint4(ph[4], ph[5], ph[6], ph[7]);
    *(uint4*)(g_fc1l + o)     = make_uint4(pl[0], pl[1], pl[2], pl[3]);
    *(uint4*)(g_fc1l + o + 8) = make_uint4(pl[4], pl[5], pl[6], pl[7]);
}

// FAST layer-2 (b1==0): thread per node. 8B float2 gathers, rank-2 expansion.
__global__ void __launch_bounds__(256) k_l2f(const float* __restrict__ b2, int n) {
    if (g_b1nz) return;
    __shared__ float Ps[64], Qs[64], Bs[64];
    int t = threadIdx.x;
    if (t < 64) { Ps[t] = g_P[t]; Qs[t] = g_Q[t]; Bs[t] = b2[t]; }
    __syncthreads();
    int i = blockIdx.x * blockDim.x + t;
    if (i >= n) return;
    int c = g_cnt[i];
    int m = c < CAP ? c : CAP;
    float Ap = 0.f, An = 0.f;
    int j = 0;
    for (; j + 8 <= m; j += 8) {
        int ss[8];
#pragma unroll
        for (int q = 0; q < 8; q++) ss[q] = g_slots[(size_t)(j + q) * NN + i];
#pragma unroll
        for (int q = 0; q < 8; q++) {
            float2 v = g_ac[ss[q]];
            Ap += v.x; An += v.y;
        }
    }
    for (; j < m; j++) {
        float2 v = g_ac[g_slots[(size_t)j * NN + i]];
        Ap += v.x; An += v.y;
    }
    if (c > CAP) {
        int on = g_ovf_n; if (on > OVF_CAP) on = OVF_CAP;
        for (int e = 0; e < on; e++)
            if (g_ovf_dst[e] == i) {
                float2 v = g_ac[g_ovf_src[e]];
                Ap += v.x; An += v.y;
            }
    }
    float2 me = g_ac[i];
    float di = g_dinv[i];
    float s1 = di * (Ap + me.x);
    float s2 = di * (An + me.y);
    int g = i / 784, p = i - g * 784;
    size_t o = (size_t)g * KTOT + p * 64;
#pragma unroll
    for (int jb = 0; jb < 64; jb += 8) {
        uint32_t ph[4], pl[4];
#pragma unroll
        for (int q = 0; q < 4; q++) {
            int jj = jb + 2 * q;
            float v0 = fmaxf(s1 * Ps[jj]     + s2 * Qs[jj]     + Bs[jj],     0.f);
            float v1 = fmaxf(s1 * Ps[jj + 1] + s2 * Qs[jj + 1] + Bs[jj + 1], 0.f);
            __nv_bfloat16 h0, l0, h1, l1;
            split_bf16(v0, h0, l0);
            split_bf16(v1, h1, l1);
            ph[q] = (uint32_t)__bfloat16_as_ushort(h0) | ((uint32_t)__bfloat16_as_ushort(h1) << 16);
            pl[q] = (uint32_t)__bfloat16_as_ushort(l0) | ((uint32_t)__bfloat16_as_ushort(l1) << 16);
        }
        *(uint4*)(g_h2h + o + jb) = make_uint4(ph[0], ph[1], ph[2], ph[3]);
        *(uint4*)(g_h2l + o + jb) = make_uint4(pl[0], pl[1], pl[2], pl[3]);
    }
}

// FALLBACK layer-2 (b1!=0): round-8 generic warp-gather path.
__global__ void __launch_bounds__(256) k_l2(const float* __restrict__ W2,
                                            const float* __restrict__ b2) {
    if (!g_b1nz) return;
    __shared__ u64  w2p[32 * 32];
    __shared__ float h2t[32][65];
    __shared__ float b2s[64];
    int t = threadIdx.x;
    for (int idx = t; idx < 1024; idx += 256) {
        int f = idx >> 5, l = idx & 31;
        w2p[idx] = pack2(W2[f * 64 + l], W2[f * 64 + l + 32]);
    }
    if (t < 64) b2s[t] = b2[t];
    __syncthreads();

    int warp = t >> 5, lane = t & 31;
    int p = blockIdx.x;
    int gblk = blockIdx.y;

#pragma unroll 1
    for (int q = 0; q < 4; q++) {
        int gl = warp * 4 + q;
        int i = (gblk * 32 + gl) * 784 + p;
        float di = g_dinv[i];
        int c = g_cnt[i];
        int m = c < CAP ? c : CAP;
        float acc = 0.f;
        int j = 0;
        for (; j + 8 <= m; j += 8) {
            int ss[8];
#pragma unroll
            for (int qq = 0; qq < 8; qq++) ss[qq] = g_slots[(size_t)(j + qq) * NN + i];
            float v[8];
#pragma unroll
            for (int qq = 0; qq < 8; qq++) v[qq] = g_h1[(size_t)ss[qq] * 32 + lane];
            acc += ((v[0] + v[1]) + (v[2] + v[3])) + ((v[4] + v[5]) + (v[6] + v[7]));
        }
        for (; j < m; j++)
            acc += g_h1[(size_t)g_slots[(size_t)j * NN + i] * 32 + lane];
        if (c > CAP) {
            int on = g_ovf_n; if (on > OVF_CAP) on = OVF_CAP;
            for (int e = 0; e < on; e++)
                if (g_ovf_dst[e] == i)
                    acc += g_h1[(size_t)g_ovf_src[e] * 32 + lane];
        }
        float u = di * (acc + g_h1[(size_t)i * 32 + lane]);

        u64 o0 = pack2(b2s[lane], b2s[lane + 32]);
        u64 o1 = 0ull;
#pragma unroll
        for (int f = 0; f < 32; f += 2) {
            float uf0 = __shfl_sync(0xffffffffu, u, f);
            float uf1 = __shfl_sync(0xffffffffu, u, f + 1);
            ffma2(o0, pack2(uf0, uf0), w2p[f * 32 + lane]);
            ffma2(o1, pack2(uf1, uf1), w2p[(f + 1) * 32 + lane]);
        }
        float2 a0 = unpack2(o0), a1 = unpack2(o1);
        h2t[gl][lane]      = fmaxf(a0.x + a1.x, 0.f);
        h2t[gl][lane + 32] = fmaxf(a0.y + a1.y, 0.f);
    }
    __syncthreads();
    for (int idx = t; idx < 512; idx += 256) {
        int gl = idx >> 4, f4 = (idx & 15) * 4;
        uint32_t ph[2], pl[2];
#pragma unroll
        for (int q = 0; q < 2; q++) {
            __nv_bfloat16 h0, l0, h1, l1;
            split_bf16(h2t[gl][f4 + 2 * q], h0, l0);
            split_bf16(h2t[gl][f4 + 2 * q + 1], h1, l1);
            ph[q] = (uint32_t)__bfloat16_as_ushort(h0) | ((uint32_t)__bfloat16_as_ushort(h1) << 16);
            pl[q] = (uint32_t)__bfloat16_as_ushort(l0) | ((uint32_t)__bfloat16_as_ushort(l1) << 16);
        }
        size_t o = (size_t)(gblk * 32 + gl) * KTOT + p * 64 + f4;
        *(uint2*)(g_h2h + o) = make_uint2(ph[0], ph[1]);
        *(uint2*)(g_h2l + o) = make_uint2(pl[0], pl[1]);
    }
}

// HMMA bf16-split GEMM (mma.sync m16n8k16): C[512x128] = A[512xK] B[Kx128],
// C ≈ Ah·Bh + Ah·Bl + Al·Bh, fp32 accumulate. Split-K over 37 partitions.
#define HG_BUF 40960     // bytes per double-buffer half (4 arrays x 128 rows x 80B)
__global__ void __launch_bounds__(256) k_hgemm() {
    extern __shared__ __align__(16) char sm[];
    const int t = threadIdx.x;
    const int warp = t >> 5, lane = t & 31;
    const int warpM = warp & 3, warpN = warp >> 2;
    const int g0 = blockIdx.x * 128;
    const int sp = blockIdx.y;
    const int t0 = sp * 42 + (sp < 14 ? sp : 14);
    const int ntc = 42 + (sp < 14 ? 1 : 0);

    const uint32_t sb = smem_u32(sm);

    float C[2][8][4];
#pragma unroll
    for (int a = 0; a < 2; a++)
#pragma unroll
        for (int bq = 0; bq < 8; bq++)
#pragma unroll
            for (int cq = 0; cq < 4; cq++) C[a][bq][cq] = 0.f;

    auto load_chunk = [&](int ch, int buf) {
        const size_t kb = (size_t)(t0 + ch) * 32;
        const uint32_t base = sb + buf * HG_BUF;
#pragma unroll
        for (int i = 0; i < 8; i++) {
            int v = t + i * 256;
            int arr = v >> 9, rem = v & 511;
            int row = rem >> 2, c16 = rem & 3;
            uint32_t dst = base + arr * 10240 + row * 80 + c16 * 16;
            const __nv_bfloat16* src;
            if (arr == 0)      src = g_h2h  + (size_t)(g0 + row) * KTOT + kb + c16 * 8;
            else if (arr == 1) src = g_h2l  + (size_t)(g0 + row) * KTOT + kb + c16 * 8;
            else if (arr == 2) src = g_fc1h + (size_t)row * KTOT + kb + c16 * 8;
            else               src = g_fc1l + (size_t)row * KTOT + kb + c16 * 8;
            cp16s(dst, src);
        }
        CP_COMMIT();
    };

    load_chunk(0, 0);

#pragma unroll 1
    for (int ch = 0; ch < ntc; ch++) {
        if (ch + 1 < ntc) {
            load_chunk(ch + 1, (ch + 1) & 1);
            CP_WAIT(1);
        } else {
            CP_WAIT(0);
        }
        __syncthreads();

        const uint32_t bufB = sb + (ch & 1) * HG_BUF;
#pragma unroll
        for (int k16 = 0; k16 < 2; k16++) {
            const uint32_t kOff = (k16 * 16 + ((lane >> 4) << 3)) * 2;
            uint32_t ah[2][4], al[2][4];
#pragma unroll
            for (int mt = 0; mt < 2; mt++) {
                uint32_t rowo = (warpM * 32 + mt * 16 + (lane & 15)) * 80 + kOff;
                ldsm4(ah[mt], bufB + rowo);
                ldsm4(al[mt], bufB + 10240 + rowo);
            }
            uint32_t bh[8][2], bl[8][2];
#pragma unroll
            for (int ntp = 0; ntp < 4; ntp++) {
                uint32_t rowo = (warpN * 64 + ntp * 16 + (lane & 15)) * 80 + kOff;
                uint32_t q[4];
                ldsm4(q, bufB + 20480 + rowo);
                bh[2 * ntp][0] = q[0]; bh[2 * ntp][1] = q[2];
                bh[2 * ntp + 1][0] = q[1]; bh[2 * ntp + 1][1] = q[3];
                ldsm4(q, bufB + 30720 + rowo);
                bl[2 * ntp][0] = q[0]; bl[2 * ntp][1] = q[2];
                bl[2 * ntp + 1][0] = q[1]; bl[2 * ntp + 1][1] = q[3];
            }
#pragma unroll
            for (int mt = 0; mt < 2; mt++)
#pragma unroll
                for (int nt = 0; nt < 8; nt++) {
                    mma_bf16(C[mt][nt], ah[mt], bh[nt]);
                    mma_bf16(C[mt][nt], ah[mt], bl[nt]);
                    mma_bf16(C[mt][nt], al[mt], bh[nt]);
                }
        }
        __syncthreads();
    }

#pragma unroll
    for (int mt = 0; mt < 2; mt++) {
        int r0 = g0 + warpM * 32 + mt * 16 + (lane >> 2);
#pragma unroll
        for (int nt = 0; nt < 8; nt++) {
            int col = warpN * 64 + nt * 8 + (lane & 3) * 2;
            float* d = &g_part[((size_t)sp * NGRAPH + r0) * 128 + col];
            *(float2*)d             = make_float2(C[mt][nt][0], C[mt][nt][1]);
            *(float2*)(d + 8 * 128) = make_float2(C[mt][nt][2], C[mt][nt][3]);
        }
    }
}

// Reduce partials + fc1 bias + relu + fc2
__global__ void k_final(const float* __restrict__ fc1_b,
                        const float* __restrict__ fc2_w,
                        const float* __restrict__ fc2_b,
                        float* __restrict__ out) {
    int g = blockIdx.x;     // 512
    int j = threadIdx.x;    // 128
    float v = fc1_b[j];
#pragma unroll 2
    for (int s = 0; s < SPLITS; s++)
        v += g_part[((size_t)s * NGRAPH + g) * 128 + j];
    v = fmaxf(v, 0.f);
    __shared__ float f1[128];
    f1[j] = v;
    __syncthreads();
    if (j < 10) {
        float o = fc2_b[j];
#pragma unroll 16
        for (int tt = 0; tt < 128; tt++) o += f1[tt] * fc2_w[tt * 10 + j];
        out[g * 10 + j] = o;
    }
}

// ---------------- host launcher ----------------
extern "C" void kernel_launch(void* const* d_in, const int* in_sizes, int n_in,
                              void* d_out, int out_size) {
    const float* x     = (const float*)d_in[0];
    const int*   ei    = (const int*)d_in[1];     // int32 OR int64 (auto-detected)
    const float* W1    = (const float*)d_in[2];
    const float* b1    = (const float*)d_in[3];
    const float* W2    = (const float*)d_in[4];
    const float* b2    = (const float*)d_in[5];
    const float* fc1_w = (const float*)d_in[6];
    const float* fc1_b = (const float*)d_in[7];
    const float* fc2_w = (const float*)d_in[8];
    const float* fc2_b = (const float*)d_in[9];
    float* out = (float*)d_out;

    int n = in_sizes[0];          // 401408
    int E = in_sizes[1] / 2;      // 3211264

    static int smem_set = 0;
    if (!smem_set) {
        cudaFuncSetAttribute(k_hgemm, cudaFuncAttributeMaxDynamicSharedMemorySize,
                             2 * HG_BUF);
        smem_set = 1;
    }

    k_init<<<1568, 256>>>(ei, b1, n);
    k_count<<<(E + 255) / 256, 256>>>(ei, E);
    k_dinv<<<(n + 255) / 256, 256>>>(x, n);
    k_pq<<<1, 64>>>(W1, W2);
    k_l1<<<(n + 255) / 256, 256>>>(W1, b1, n);
    k_cvtB<<<1568, 256>>>(fc1_w);
    k_l2f<<<(n + 255) / 256, 256>>>(b2, n);
    k_l2<<<dim3(784, 16), 256>>>(W2, b2);
    k_hgemm<<<dim3(4, SPLITS), 256, 2 * HG_BUF>>>();
    k_final<<<NGRAPH, 128>>>(fc1_b, fc2_w, fc2_b, out);
}

// round 10
// speedup vs baseline: 3.0399x; 1.4140x over previous
#include <cuda_runtime.h>
#include <cuda_bf16.h>
#include <cuda_fp16.h>
#include <cstdint>

// Problem constants (fixed by the dataset)
#define NN     401408          // nodes
#define EE     3211264         // edges
#define CAP    40              // slots per node (indegree ~ Poisson(8))
#define OVF_CAP 65536
#define KTOT   50176           // 784*64
#define NGRAPH 512
#define SPLITS 37              // split-K partitions over 1568 K-chunks of 32

typedef unsigned long long u64;

// ---------------- device scratch (static, no allocations) ----------------
__device__ int   g_cnt[NN];
__device__ float g_dinv[NN];
__device__ float g_xd[NN];                                     // x*dinv
__device__ int   g_slots[(size_t)CAP * NN];                    // slot-major
__device__ __align__(16) float g_h1[(size_t)NN * 32];          // PRESCALED by dinv (fallback path)
__device__ __align__(8)  float2 g_ac[NN];                      // (relu(tt)*di, min(tt,0)*di)
__device__ float g_P[64], g_Q[64];
__device__ __align__(16) __half g_h2f[(size_t)NGRAPH * KTOT];  // A fp16 [g][k]
__device__ __align__(16) __half g_fc1f[(size_t)128 * KTOT];    // B^T fp16 [n][k]
__device__ __align__(16) float g_part[(size_t)SPLITS * NGRAPH * 128];
__device__ int   g_ovf_n;
__device__ int   g_is64;
__device__ int   g_b1nz;
__device__ int   g_ovf_src[OVF_CAP];
__device__ int   g_ovf_dst[OVF_CAP];

// ---------------- ptx helpers ----------------
__device__ __forceinline__ u64 pack2(float lo, float hi) {
    u64 r; asm("mov.b64 %0, {%1, %2};" : "=l"(r) : "f"(lo), "f"(hi)); return r;
}
__device__ __forceinline__ float2 unpack2(u64 v) {
    float2 f; asm("mov.b64 {%0, %1}, %2;" : "=f"(f.x), "=f"(f.y) : "l"(v)); return f;
}
__device__ __forceinline__ void ffma2(u64& d, u64 a, u64 b) {
    asm("fma.rn.f32x2 %0, %1, %2, %0;" : "+l"(d) : "l"(a), "l"(b));
}
__device__ __forceinline__ void cp16s(uint32_t sa, const void* g) {
    asm volatile("cp.async.cg.shared.global [%0], [%1], 16;" :: "r"(sa), "l"(g));
}
#define CP_COMMIT() asm volatile("cp.async.commit_group;")
#define CP_WAIT(n)  asm volatile("cp.async.wait_group %0;" :: "n"(n))

__device__ __forceinline__ uint32_t smem_u32(const void* p) {
    uint32_t a;
    asm("{ .reg .u64 t; cvta.to.shared.u64 t, %1; cvt.u32.u64 %0, t; }" : "=r"(a) : "l"(p));
    return a;
}
__device__ __forceinline__ void ldsm4(uint32_t* r, uint32_t a) {
    asm volatile("ldmatrix.sync.aligned.m8n8.x4.shared.b16 {%0,%1,%2,%3}, [%4];"
                 : "=r"(r[0]), "=r"(r[1]), "=r"(r[2]), "=r"(r[3]) : "r"(a));
}
__device__ __forceinline__ void mma_f16(float* c, const uint32_t* a, const uint32_t* b) {
    asm volatile(
        "mma.sync.aligned.m16n8k16.row.col.f32.f16.f16.f32 "
        "{%0,%1,%2,%3}, {%4,%5,%6,%7}, {%8,%9}, {%0,%1,%2,%3};"
        : "+f"(c[0]), "+f"(c[1]), "+f"(c[2]), "+f"(c[3])
        : "r"(a[0]), "r"(a[1]), "r"(a[2]), "r"(a[3]), "r"(b[0]), "r"(b[1]));
}
__device__ __forceinline__ uint32_t h2pack(float a, float b) {
    __half2 h = __floats2half2_rn(a, b);
    return *(uint32_t*)&h;
}

// ---------------- kernels ----------------

// Zero counts + detect edge dtype + detect b1==0 (enables rank-2 fast path).
__global__ void k_init(const int* __restrict__ ei, const float* __restrict__ b1, int n) {
    if (blockIdx.x == 0 && threadIdx.x == 0) {
        g_ovf_n = 0;
        int ok = 1;
        for (int i = 0; i < 64; i++)
            if (ei[2 * i + 1] != 0) { ok = 0; break; }
        g_is64 = ok;
        int nz = 0;
        for (int f = 0; f < 32; f++)
            if (b1[f] != 0.0f) { nz = 1; break; }
        g_b1nz = nz;
    }
    for (int i = blockIdx.x * blockDim.x + threadIdx.x; i < n;
         i += gridDim.x * blockDim.x)
        g_cnt[i] = 0;
}

// Count in-degree and fill slot-major per-node slot table with sources.
__global__ void k_count(const int* __restrict__ ei, int E) {
    int e = blockIdx.x * blockDim.x + threadIdx.x;
    if (e >= E) return;
    int s, d;
    if (g_is64) {
        const int2* p = (const int2*)ei;
        s = p[e].x;
        d = p[(size_t)E + e].x;
    } else {
        s = ei[e];
        d = ei[(size_t)E + e];
    }
    if ((unsigned)s >= (unsigned)NN || (unsigned)d >= (unsigned)NN) return;
    int c = atomicAdd(&g_cnt[d], 1);
    if (c < CAP) {
        g_slots[(size_t)c * NN + d] = s;
    } else {
        int o = atomicAdd(&g_ovf_n, 1);
        if (o < OVF_CAP) { g_ovf_src[o] = s; g_ovf_dst[o] = d; }
    }
}

__global__ void k_dinv(const float* __restrict__ x, int n) {
    int i = blockIdx.x * blockDim.x + threadIdx.x;
    if (i < n) {
        float di = rsqrtf(1.0f + (float)g_cnt[i]);
        g_dinv[i] = di;
        g_xd[i] = x[i] * di;
    }
}

// P_j = sum_{w_f>0} W2[f,j]*w_f ; Q_j = sum_{w_f<0} W2[f,j]*w_f  (parallel)
__global__ void k_pq(const float* __restrict__ W1, const float* __restrict__ W2) {
    __shared__ float sp[4][64], sq[4][64];
    int t = threadIdx.x;           // 256
    int j = t & 63, fg = t >> 6;   // 4 groups of 8 f-rows
    float p = 0.f, q = 0.f;
#pragma unroll
    for (int ff = 0; ff < 8; ff++) {
        int f = fg * 8 + ff;
        float w = W1[f], v = W2[f * 64 + j];
        if (w > 0.f) p += v * w; else q += v * w;
    }
    sp[fg][j] = p; sq[fg][j] = q;
    __syncthreads();
    if (fg == 0) {
        g_P[j] = (sp[0][j] + sp[1][j]) + (sp[2][j] + sp[3][j]);
        g_Q[j] = (sq[0][j] + sq[1][j]) + (sq[2][j] + sq[3][j]);
    }
}

// Fused layer-1: scalar aggregate (xd gather, MLP=8).
// Fast path (b1==0): store only (ap,an). Fallback: full 32-feat h1 expansion.
__global__ void k_l1(const float* __restrict__ W1,
                     const float* __restrict__ b1, int n) {
    __shared__ float w[32], b[32];
    if (threadIdx.x < 32) { w[threadIdx.x] = W1[threadIdx.x]; b[threadIdx.x] = b1[threadIdx.x]; }
    __syncthreads();
    int i = blockIdx.x * blockDim.x + threadIdx.x;
    if (i >= n) return;
    int c = g_cnt[i];
    int m = c < CAP ? c : CAP;
    float sum = 0.f;
    int j = 0;
    for (; j + 8 <= m; j += 8) {
        int ss[8];
#pragma unroll
        for (int q = 0; q < 8; q++) ss[q] = g_slots[(size_t)(j + q) * NN + i];
        float v[8];
#pragma unroll
        for (int q = 0; q < 8; q++) v[q] = g_xd[ss[q]];
        sum += ((v[0] + v[1]) + (v[2] + v[3])) + ((v[4] + v[5]) + (v[6] + v[7]));
    }
    for (; j + 4 <= m; j += 4) {
        int s0 = g_slots[(size_t)(j + 0) * NN + i];
        int s1 = g_slots[(size_t)(j + 1) * NN + i];
        int s2 = g_slots[(size_t)(j + 2) * NN + i];
        int s3 = g_slots[(size_t)(j + 3) * NN + i];
        sum += (g_xd[s0] + g_xd[s1]) + (g_xd[s2] + g_xd[s3]);
    }
    for (; j < m; j++) sum += g_xd[g_slots[(size_t)j * NN + i]];
    if (c > CAP) {   // exactness path; essentially never taken
        int on = g_ovf_n; if (on > OVF_CAP) on = OVF_CAP;
        for (int e = 0; e < on; e++)
            if (g_ovf_dst[e] == i) sum += g_xd[g_ovf_src[e]];
    }
    float di = g_dinv[i];
    float tt = di * sum + g_xd[i] * di;
    if (!g_b1nz) {
        g_ac[i] = make_float2(fmaxf(tt, 0.f) * di, fminf(tt, 0.f) * di);
        return;
    }
    float4* dst = (float4*)(g_h1 + (size_t)i * 32);
#pragma unroll
    for (int q = 0; q < 8; q++) {
        int f = q * 4;
        float4 r;
        r.x = fmaxf(tt * w[f + 0] + b[f + 0], 0.f) * di;
        r.y = fmaxf(tt * w[f + 1] + b[f + 1], 0.f) * di;
        r.z = fmaxf(tt * w[f + 2] + b[f + 2], 0.f) * di;
        r.w = fmaxf(tt * w[f + 3] + b[f + 3], 0.f) * di;
        dst[q] = r;
    }
}

// Transpose + fp16 convert fc1_w [k][n] -> g_fc1f [n][k]
__global__ void __launch_bounds__(256) k_cvtB(const float* __restrict__ B) {
    __shared__ float tile[32][129];
    int k0 = blockIdx.x * 32;
    int t = threadIdx.x;
    for (int idx = t; idx < 4096; idx += 256) {
        int kr = idx >> 7, nn = idx & 127;
        tile[kr][nn] = B[(size_t)(k0 + kr) * 128 + nn];
    }
    __syncthreads();
    int n = t >> 1, ks = (t & 1) * 16;
    uint32_t ph[8];
#pragma unroll
    for (int q = 0; q < 8; q++)
        ph[q] = h2pack(tile[ks + 2 * q][n], tile[ks + 2 * q + 1][n]);
    size_t o = (size_t)n * KTOT + k0 + ks;
    *(uint4*)(g_fc1f + o)     = make_uint4(ph[0], ph[1], ph[2], ph[3]);
    *(uint4*)(g_fc1f + o + 8) = make_uint4(ph[4], ph[5], ph[6], ph[7]);
}

// FAST layer-2 (b1==0): thread per node. 8B float2 gathers, rank-2 expansion,
// fp16 write-out (single precision pass; error budget analyzed in notes).
__global__ void __launch_bounds__(256) k_l2f(const float* __restrict__ b2, int n) {
    if (g_b1nz) return;
    __shared__ float Ps[64], Qs[64], Bs[64];
    int t = threadIdx.x;
    if (t < 64) { Ps[t] = g_P[t]; Qs[t] = g_Q[t]; Bs[t] = b2[t]; }
    __syncthreads();
    int i = blockIdx.x * blockDim.x + t;
    if (i >= n) return;
    int c = g_cnt[i];
    int m = c < CAP ? c : CAP;
    float Ap = 0.f, An = 0.f;
    int j = 0;
    for (; j + 8 <= m; j += 8) {
        int ss[8];
#pragma unroll
        for (int q = 0; q < 8; q++) ss[q] = g_slots[(size_t)(j + q) * NN + i];
#pragma unroll
        for (int q = 0; q < 8; q++) {
            float2 v = g_ac[ss[q]];
            Ap += v.x; An += v.y;
        }
    }
    for (; j < m; j++) {
        float2 v = g_ac[g_slots[(size_t)j * NN + i]];
        Ap += v.x; An += v.y;
    }
    if (c > CAP) {
        int on = g_ovf_n; if (on > OVF_CAP) on = OVF_CAP;
        for (int e = 0; e < on; e++)
            if (g_ovf_dst[e] == i) {
                float2 v = g_ac[g_ovf_src[e]];
                Ap += v.x; An += v.y;
            }
    }
    float2 me = g_ac[i];
    float di = g_dinv[i];
    float s1 = di * (Ap + me.x);
    float s2 = di * (An + me.y);
    int g = i / 784, p = i - g * 784;
    size_t o = (size_t)g * KTOT + p * 64;
#pragma unroll
    for (int jb = 0; jb < 64; jb += 8) {
        uint32_t ph[4];
#pragma unroll
        for (int q = 0; q < 4; q++) {
            int jj = jb + 2 * q;
            float v0 = fmaxf(s1 * Ps[jj]     + s2 * Qs[jj]     + Bs[jj],     0.f);
            float v1 = fmaxf(s1 * Ps[jj + 1] + s2 * Qs[jj + 1] + Bs[jj + 1], 0.f);
            ph[q] = h2pack(v0, v1);
        }
        *(uint4*)(g_h2f + o + jb) = make_uint4(ph[0], ph[1], ph[2], ph[3]);
    }
}

// FALLBACK layer-2 (b1!=0): generic warp-gather path, fp16 write-out.
__global__ void __launch_bounds__(256) k_l2(const float* __restrict__ W2,
                                            const float* __restrict__ b2) {
    if (!g_b1nz) return;
    __shared__ u64  w2p[32 * 32];
    __shared__ float h2t[32][65];
    __shared__ float b2s[64];
    int t = threadIdx.x;
    for (int idx = t; idx < 1024; idx += 256) {
        int f = idx >> 5, l = idx & 31;
        w2p[idx] = pack2(W2[f * 64 + l], W2[f * 64 + l + 32]);
    }
    if (t < 64) b2s[t] = b2[t];
    __syncthreads();

    int warp = t >> 5, lane = t & 31;
    int p = blockIdx.x;
    int gblk = blockIdx.y;

#pragma unroll 1
    for (int q = 0; q < 4; q++) {
        int gl = warp * 4 + q;
        int i = (gblk * 32 + gl) * 784 + p;
        float di = g_dinv[i];
        int c = g_cnt[i];
        int m = c < CAP ? c : CAP;
        float acc = 0.f;
        int j = 0;
        for (; j + 8 <= m; j += 8) {
            int ss[8];
#pragma unroll
            for (int qq = 0; qq < 8; qq++) ss[qq] = g_slots[(size_t)(j + qq) * NN + i];
            float v[8];
#pragma unroll
            for (int qq = 0; qq < 8; qq++) v[qq] = g_h1[(size_t)ss[qq] * 32 + lane];
            acc += ((v[0] + v[1]) + (v[2] + v[3])) + ((v[4] + v[5]) + (v[6] + v[7]));
        }
        for (; j < m; j++)
            acc += g_h1[(size_t)g_slots[(size_t)j * NN + i] * 32 + lane];
        if (c > CAP) {
            int on = g_ovf_n; if (on > OVF_CAP) on = OVF_CAP;
            for (int e = 0; e < on; e++)
                if (g_ovf_dst[e] == i)
                    acc += g_h1[(size_t)g_ovf_src[e] * 32 + lane];
        }
        float u = di * (acc + g_h1[(size_t)i * 32 + lane]);

        u64 o0 = pack2(b2s[lane], b2s[lane + 32]);
        u64 o1 = 0ull;
#pragma unroll
        for (int f = 0; f < 32; f += 2) {
            float uf0 = __shfl_sync(0xffffffffu, u, f);
            float uf1 = __shfl_sync(0xffffffffu, u, f + 1);
            ffma2(o0, pack2(uf0, uf0), w2p[f * 32 + lane]);
            ffma2(o1, pack2(uf1, uf1), w2p[(f + 1) * 32 + lane]);
        }
        float2 a0 = unpack2(o0), a1 = unpack2(o1);
        h2t[gl][lane]      = fmaxf(a0.x + a1.x, 0.f);
        h2t[gl][lane + 32] = fmaxf(a0.y + a1.y, 0.f);
    }
    __syncthreads();
    for (int idx = t; idx < 512; idx += 256) {
        int gl = idx >> 4, f4 = (idx & 15) * 4;
        uint32_t p0 = h2pack(h2t[gl][f4],     h2t[gl][f4 + 1]);
        uint32_t p1 = h2pack(h2t[gl][f4 + 2], h2t[gl][f4 + 3]);
        size_t o = (size_t)(gblk * 32 + gl) * KTOT + p * 64 + f4;
        *(uint2*)(g_h2f + o) = make_uint2(p0, p1);
    }
}

// HMMA fp16 GEMM (mma.sync m16n8k16): C[512x128] = A[512xK] B[Kx128],
// fp32 accumulate. Split-K over 37 partitions of K-chunks (32 fp16).
// grid (4 M-tiles, 37) = 148 CTAs, 256 thr (8 warps, 4Mx2N).
// smem rows: 32 fp16 = 64B data in 80B stride (bank-conflict-free ldmatrix).
#define HG_BUF 20480     // bytes per double-buffer half (2 arrays x 128 rows x 80B)
__global__ void __launch_bounds__(256) k_hgemm() {
    extern __shared__ __align__(16) char sm[];
    const int t = threadIdx.x;
    const int warp = t >> 5, lane = t & 31;
    const int warpM = warp & 3, warpN = warp >> 2;
    const int g0 = blockIdx.x * 128;
    const int sp = blockIdx.y;
    const int t0 = sp * 42 + (sp < 14 ? sp : 14);
    const int ntc = 42 + (sp < 14 ? 1 : 0);

    const uint32_t sb = smem_u32(sm);

    float C[2][8][4];
#pragma unroll
    for (int a = 0; a < 2; a++)
#pragma unroll
        for (int bq = 0; bq < 8; bq++)
#pragma unroll
            for (int cq = 0; cq < 4; cq++) C[a][bq][cq] = 0.f;

    auto load_chunk = [&](int ch, int buf) {
        const size_t kb = (size_t)(t0 + ch) * 32;
        const uint32_t base = sb + buf * HG_BUF;
#pragma unroll
        for (int i = 0; i < 4; i++) {
            int v = t + i * 256;
            int arr = v >> 9, rem = v & 511;
            int row = rem >> 2, c16 = rem & 3;
            uint32_t dst = base + arr * 10240 + row * 80 + c16 * 16;
            const __half* src = (arr == 0)
                ? g_h2f  + (size_t)(g0 + row) * KTOT + kb + c16 * 8
                : g_fc1f + (size_t)row * KTOT + kb + c16 * 8;
            cp16s(dst, src);
        }
        CP_COMMIT();
    };

    load_chunk(0, 0);

#pragma unroll 1
    for (int ch = 0; ch < ntc; ch++) {
        if (ch + 1 < ntc) {
            load_chunk(ch + 1, (ch + 1) & 1);
            CP_WAIT(1);
        } else {
            CP_WAIT(0);
        }
        __syncthreads();

        const uint32_t bufB = sb + (ch & 1) * HG_BUF;
#pragma unroll
        for (int k16 = 0; k16 < 2; k16++) {
            const uint32_t kOff = (k16 * 16 + ((lane >> 4) << 3)) * 2;
            uint32_t ah[2][4];
#pragma unroll
            for (int mt = 0; mt < 2; mt++) {
                uint32_t rowo = (warpM * 32 + mt * 16 + (lane & 15)) * 80 + kOff;
                ldsm4(ah[mt], bufB + rowo);
            }
            uint32_t bh[8][2];
#pragma unroll
            for (int ntp = 0; ntp < 4; ntp++) {
                uint32_t rowo = (warpN * 64 + ntp * 16 + (lane & 15)) * 80 + kOff;
                uint32_t q[4];
                ldsm4(q, bufB + 10240 + rowo);
                bh[2 * ntp][0] = q[0]; bh[2 * ntp][1] = q[2];
                bh[2 * ntp + 1][0] = q[1]; bh[2 * ntp + 1][1] = q[3];
            }
#pragma unroll
            for (int mt = 0; mt < 2; mt++)
#pragma unroll
                for (int nt = 0; nt < 8; nt++)
                    mma_f16(C[mt][nt], ah[mt], bh[nt]);
        }
        __syncthreads();
    }

#pragma unroll
    for (int mt = 0; mt < 2; mt++) {
        int r0 = g0 + warpM * 32 + mt * 16 + (lane >> 2);
#pragma unroll
        for (int nt = 0; nt < 8; nt++) {
            int col = warpN * 64 + nt * 8 + (lane & 3) * 2;
            float* d = &g_part[((size_t)sp * NGRAPH + r0) * 128 + col];
            *(float2*)d             = make_float2(C[mt][nt][0], C[mt][nt][1]);
            *(float2*)(d + 8 * 128) = make_float2(C[mt][nt][2], C[mt][nt][3]);
        }
    }
}

// Reduce partials + fc1 bias + relu + fc2
__global__ void k_final(const float* __restrict__ fc1_b,
                        const float* __restrict__ fc2_w,
                        const float* __restrict__ fc2_b,
                        float* __restrict__ out) {
    int g = blockIdx.x;     // 512
    int j = threadIdx.x;    // 128
    float v = fc1_b[j];
#pragma unroll 2
    for (int s = 0; s < SPLITS; s++)
        v += g_part[((size_t)s * NGRAPH + g) * 128 + j];
    v = fmaxf(v, 0.f);
    __shared__ float f1[128];
    f1[j] = v;
    __syncthreads();
    if (j < 10) {
        float o = fc2_b[j];
#pragma unroll 16
        for (int tt = 0; tt < 128; tt++) o += f1[tt] * fc2_w[tt * 10 + j];
        out[g * 10 + j] = o;
    }
}

// ---------------- host launcher ----------------
extern "C" void kernel_launch(void* const* d_in, const int* in_sizes, int n_in,
                              void* d_out, int out_size) {
    const float* x     = (const float*)d_in[0];
    const int*   ei    = (const int*)d_in[1];     // int32 OR int64 (auto-detected)
    const float* W1    = (const float*)d_in[2];
    const float* b1    = (const float*)d_in[3];
    const float* W2    = (const float*)d_in[4];
    const float* b2    = (const float*)d_in[5];
    const float* fc1_w = (const float*)d_in[6];
    const float* fc1_b = (const float*)d_in[7];
    const float* fc2_w = (const float*)d_in[8];
    const float* fc2_b = (const float*)d_in[9];
    float* out = (float*)d_out;

    int n = in_sizes[0];          // 401408
    int E = in_sizes[1] / 2;      // 3211264

    static int smem_set = 0;
    if (!smem_set) {
        cudaFuncSetAttribute(k_hgemm, cudaFuncAttributeMaxDynamicSharedMemorySize,
                             2 * HG_BUF);
        smem_set = 1;
    }

    k_init<<<1568, 256>>>(ei, b1, n);
    k_count<<<(E + 255) / 256, 256>>>(ei, E);
    k_dinv<<<(n + 255) / 256, 256>>>(x, n);
    k_pq<<<1, 256>>>(W1, W2);
    k_l1<<<(n + 255) / 256, 256>>>(W1, b1, n);
    k_cvtB<<<1568, 256>>>(fc1_w);
    k_l2f<<<(n + 255) / 256, 256>>>(b2, n);
    k_l2<<<dim3(784, 16), 256>>>(W2, b2);
    k_hgemm<<<dim3(4, SPLITS), 256, 2 * HG_BUF>>>();
    k_final<<<NGRAPH, 128>>>(fc1_b, fc2_w, fc2_b, out);
}